// round 4
// baseline (speedup 1.0000x reference)
#include <cuda_runtime.h>
#include <math.h>

// Problem constants
#define BB 2
#define TT 128
#define DD 1024
#define HH 8
#define RRm 8
#define DK 64
#define DV 64
#define NPROJ 2176           // 512 q | 512 k | 512 v | 64 beta | 64 tg | 512 g
#define NROWS 256            // B*T

typedef unsigned long long u64;

// Scratch (no allocations allowed)
__device__ __align__(16) float g_proj[NROWS * NPROJ];          // 2.2 MB
__device__ __align__(16) float g_yr[RRm * NROWS * 512];        // 4 MB  (per-r mode reads)
__device__ __align__(16) float g_a[NROWS * 512];               // 512 KB (gated, r-reduced)

// ---------------------------------------------------------------------------
// f32x2 helpers (ptxas never emits FFMA2 from C++; PTX only)
// ---------------------------------------------------------------------------
__device__ __forceinline__ u64 pack2(float lo, float hi) {
  u64 r; asm("mov.b64 %0, {%1, %2};" : "=l"(r) : "f"(lo), "f"(hi)); return r;
}
__device__ __forceinline__ void unpack2(u64 v, float& lo, float& hi) {
  asm("mov.b64 {%0, %1}, %2;" : "=f"(lo), "=f"(hi) : "l"(v));
}
__device__ __forceinline__ u64 fma2(u64 a, u64 b, u64 c) {
  u64 d; asm("fma.rn.f32x2 %0, %1, %2, %3;" : "=l"(d) : "l"(a), "l"(b), "l"(c)); return d;
}
__device__ __forceinline__ u64 mul2(u64 a, u64 b) {
  u64 d; asm("mul.rn.f32x2 %0, %1, %2;" : "=l"(d) : "l"(a), "l"(b)); return d;
}
__device__ __forceinline__ u64 neg2(u64 a) { return a ^ 0x8000000080000000ULL; }

union F4U { float4 f; u64 u[2]; };

__device__ __forceinline__ float sigmoidf_(float x) { return 1.f / (1.f + expf(-x)); }

// ===========================================================================
// GEMM tile body: 16 rows x 64 cols, k-depth 32, double-buffered smem.
// 256 threads. Per thread: 1 row (ty = tid>>4) x 4 cols (tx = tid&15).
// A loads: threads 0..127, 1 float4 each. B loads: all threads, 2 float4.
// ===========================================================================

// ---------------------------------------------------------------------------
// Fused projection GEMM: proj[256, 2176] = x @ [Wq|Wk|Wv|Wb|Wtg|Wg]
// grid (34, 16) = 544 CTAs. Sigmoid for cols >= 1536.
// ---------------------------------------------------------------------------
__global__ __launch_bounds__(256) void proj_gemm_kernel(
    const float* __restrict__ x,
    const float* __restrict__ Wq, const float* __restrict__ Wk,
    const float* __restrict__ Wv, const float* __restrict__ Wb,
    const float* __restrict__ Wtg, const float* __restrict__ Wg) {
  __shared__ float As[2][32][16];
  __shared__ float Bs[2][32][64];

  const int colBase = blockIdx.x * 64;
  const int rowBase = blockIdx.y * 16;

  const float* W; int lc, ldw;
  if (colBase < 512)       { W = Wq;  lc = colBase;        ldw = 512; }
  else if (colBase < 1024) { W = Wk;  lc = colBase - 512;  ldw = 512; }
  else if (colBase < 1536) { W = Wv;  lc = colBase - 1024; ldw = 512; }
  else if (colBase < 1600) { W = Wb;  lc = colBase - 1536; ldw = 64;  }
  else if (colBase < 1664) { W = Wtg; lc = colBase - 1600; ldw = 64;  }
  else                     { W = Wg;  lc = colBase - 1664; ldw = 512; }

  const int tid = threadIdx.x;
  const int ty = tid >> 4, tx = tid & 15;        // compute: row ty, cols tx*4+
  const int lrA = tid >> 3, kgA = tid & 7;       // A load (threads 0..127)
  const int lkB = tid >> 4, c4B = (tid & 15) << 2;

  u64 acc0 = 0ULL, acc1 = 0ULL;

  const int NIT = DD / 32;
  float4 av, bv0, bv1;
  if (tid < 128) av = *(const float4*)(x + (rowBase + lrA) * DD + kgA * 4);
  bv0 = *(const float4*)(W + lkB * ldw + lc + c4B);
  bv1 = *(const float4*)(W + (lkB + 16) * ldw + lc + c4B);
  if (tid < 128) {
    As[0][kgA * 4 + 0][lrA] = av.x;
    As[0][kgA * 4 + 1][lrA] = av.y;
    As[0][kgA * 4 + 2][lrA] = av.z;
    As[0][kgA * 4 + 3][lrA] = av.w;
  }
  *(float4*)(&Bs[0][lkB][c4B]) = bv0;
  *(float4*)(&Bs[0][lkB + 16][c4B]) = bv1;
  __syncthreads();

  int cur = 0;
  for (int i = 0; i < NIT; i++) {
    if (i + 1 < NIT) {
      int kb = (i + 1) * 32;
      if (tid < 128) av = *(const float4*)(x + (rowBase + lrA) * DD + kb + kgA * 4);
      bv0 = *(const float4*)(W + (kb + lkB) * ldw + lc + c4B);
      bv1 = *(const float4*)(W + (kb + lkB + 16) * ldw + lc + c4B);
    }
#pragma unroll
    for (int kk = 0; kk < 32; kk++) {
      float a = As[cur][kk][ty];
      F4U bb; bb.f = *(float4*)(&Bs[cur][kk][tx * 4]);
      u64 a2 = pack2(a, a);
      acc0 = fma2(a2, bb.u[0], acc0);
      acc1 = fma2(a2, bb.u[1], acc1);
    }
    if (i + 1 < NIT) {
      int nxt = cur ^ 1;
      if (tid < 128) {
        As[nxt][kgA * 4 + 0][lrA] = av.x;
        As[nxt][kgA * 4 + 1][lrA] = av.y;
        As[nxt][kgA * 4 + 2][lrA] = av.z;
        As[nxt][kgA * 4 + 3][lrA] = av.w;
      }
      *(float4*)(&Bs[nxt][lkB][c4B]) = bv0;
      *(float4*)(&Bs[nxt][lkB + 16][c4B]) = bv1;
      __syncthreads();
      cur = nxt;
    }
  }

  F4U o; o.u[0] = acc0; o.u[1] = acc1;
  if (colBase >= 1536) {
    o.f.x = sigmoidf_(o.f.x); o.f.y = sigmoidf_(o.f.y);
    o.f.z = sigmoidf_(o.f.z); o.f.w = sigmoidf_(o.f.w);
  }
  *(float4*)(g_proj + (rowBase + ty) * NPROJ + colBase + tx * 4) = o.f;
}

// ---------------------------------------------------------------------------
// Sequential scan. One CTA per (b,h,r) chain: 128 CTAs, 256 threads.
// Thread owns v = tid/4 (row), k-slice [16*(tid%4), +16) as 8 f32x2 pairs.
// Software pipeline: t+1's q/k/v/beta/tg prefetched into registers while
// computing step t -> L2 latency off the serial critical path.
// ---------------------------------------------------------------------------
__global__ __launch_bounds__(256) void scan_kernel(
    const float* __restrict__ mode_logits,
    const float* __restrict__ log_decay,
    const float* __restrict__ omega_log_scale) {
  const int cid = blockIdx.x;        // 0..127
  const int b = cid >> 6;
  const int h = (cid >> 3) & 7;
  const int r = cid & 7;
  const int tid = threadIdx.x;
  const int v = tid >> 2;
  const int q4 = tid & 3;
  const int k0 = q4 * 16;

  // mode weight: softmax over R for this head
  float ml[RRm];
  float mx = -1e30f;
#pragma unroll
  for (int i = 0; i < RRm; i++) { ml[i] = mode_logits[h * RRm + i]; mx = fmaxf(mx, ml[i]); }
  float ssum = 0.f;
#pragma unroll
  for (int i = 0; i < RRm; i++) ssum += expf(ml[i] - mx);
  const float mw = expf(ml[r] - mx) / ssum;

  // rho = exp(-softplus(log_decay))
  const float ldv = log_decay[h * RRm + r];
  const float sp = (ldv > 20.f) ? ldv : log1pf(expf(ldv));
  const float rho = expf(-sp);
  const float osc = expf(omega_log_scale[h * RRm + r]);

  u64 cw2[8], sw2[8], sr2[8], si2[8];
  const float c_ln = 9.210340371976184f / 64.f;  // ln(10000)/64
#pragma unroll
  for (int p = 0; p < 8; p++) {
    float pv = (float)(k0 + 2 * p);              // even -> (k & ~1) identical for pair
    float om = osc * expf(-pv * c_ln);
    float c = cosf(om), s = sinf(om);
    cw2[p] = pack2(c, c);
    sw2[p] = pack2(s, s);
    sr2[p] = 0ULL;
    si2[p] = 0ULL;
  }

  const int qoff = h * DK + k0;
  const float* rowBase = g_proj + (b * TT) * NPROJ;
  float* ybase = g_yr + r * (NROWS * 512) + (b * TT) * 512 + h * DV + v;

  // Prefetch t = 0
  F4U kbuf[4], qbuf[4];
  float vn, betan, tgn;
#pragma unroll
  for (int g4 = 0; g4 < 4; g4++) {
    kbuf[g4].f = *(const float4*)(rowBase + 512 + qoff + g4 * 4);
    qbuf[g4].f = *(const float4*)(rowBase + qoff + g4 * 4);
  }
  vn    = rowBase[1024 + h * DV + v];
  betan = rowBase[1536 + h * RRm + r];
  tgn   = rowBase[1600 + h * RRm + r];

  for (int t = 0; t < TT; t++) {
    u64 kt2[8], qt2[8];
#pragma unroll
    for (int g4 = 0; g4 < 4; g4++) {
      kt2[g4 * 2 + 0] = kbuf[g4].u[0]; kt2[g4 * 2 + 1] = kbuf[g4].u[1];
      qt2[g4 * 2 + 0] = qbuf[g4].u[0]; qt2[g4 * 2 + 1] = qbuf[g4].u[1];
    }
    const float vtv = vn, beta = betan, tg = tgn;

    // Prefetch t+1 (independent of state -> hides L2 latency)
    if (t + 1 < TT) {
      const float* row = rowBase + (t + 1) * NPROJ;
#pragma unroll
      for (int g4 = 0; g4 < 4; g4++) {
        kbuf[g4].f = *(const float4*)(row + 512 + qoff + g4 * 4);
        qbuf[g4].f = *(const float4*)(row + qoff + g4 * 4);
      }
      vn    = row[1024 + h * DV + v];
      betan = row[1536 + h * RRm + r];
      tgn   = row[1600 + h * RRm + r];
    }

    const float decay = tg * rho;
    const u64 decay2 = pack2(decay, decay);

    // rotate state (complex mult by decay * e^{i omega}) + pred partial
    u64 predA = 0ULL, predB = 0ULL;
#pragma unroll
    for (int p = 0; p < 8; p++) {
      u64 dc = mul2(decay2, cw2[p]);
      u64 ds = mul2(decay2, sw2[p]);
      u64 m1 = mul2(ds, si2[p]);
      u64 rr = fma2(dc, sr2[p], neg2(m1));
      u64 m2 = mul2(dc, si2[p]);
      si2[p] = fma2(ds, sr2[p], m2);
      sr2[p] = rr;                       // sr temporarily holds rot_r
      if (p & 1) predB = fma2(rr, kt2[p], predB);
      else       predA = fma2(rr, kt2[p], predA);
    }
    u64 pred2; {
      float alo, ahi, blo, bhi;
      unpack2(predA, alo, ahi); unpack2(predB, blo, bhi);
      pred2 = pack2(alo + blo, ahi + bhi);
    }
    float plo, phi; unpack2(pred2, plo, phi);
    float pred = plo + phi;
    pred += __shfl_xor_sync(0xffffffffu, pred, 1);
    pred += __shfl_xor_sync(0xffffffffu, pred, 2);

    const float w = beta * (vtv - pred);
    const u64 w2 = pack2(w, w);

    u64 rdA = 0ULL, rdB = 0ULL;
#pragma unroll
    for (int p = 0; p < 8; p++) {
      sr2[p] = fma2(w2, kt2[p], sr2[p]); // sr_new = rot_r + beta*err*k
      if (p & 1) rdB = fma2(sr2[p], qt2[p], rdB);
      else       rdA = fma2(sr2[p], qt2[p], rdA);
    }
    float r0lo, r0hi, r1lo, r1hi;
    unpack2(rdA, r0lo, r0hi); unpack2(rdB, r1lo, r1hi);
    float rd = (r0lo + r1lo) + (r0hi + r1hi);
    rd += __shfl_xor_sync(0xffffffffu, rd, 1);
    rd += __shfl_xor_sync(0xffffffffu, rd, 2);

    if (q4 == 0) ybase[t * 512] = mw * rd;
  }
}

// ---------------------------------------------------------------------------
// Reduce over r + apply gate: g_a[row][c] = gate[row][c] * sum_r g_yr[r][row][c]
// ---------------------------------------------------------------------------
__global__ __launch_bounds__(256) void reduce_y_kernel() {
  int idx = blockIdx.x * blockDim.x + threadIdx.x;   // float4 index
  if (idx >= NROWS * 512 / 4) return;
  int row = idx >> 7;           // 128 float4 per row
  int c4 = (idx & 127) << 2;
  float4 s = *(const float4*)(g_yr + row * 512 + c4);
#pragma unroll
  for (int r = 1; r < RRm; r++) {
    float4 t = *(const float4*)(g_yr + r * (NROWS * 512) + row * 512 + c4);
    s.x += t.x; s.y += t.y; s.z += t.z; s.w += t.w;
  }
  float4 g = *(const float4*)(g_proj + row * NPROJ + 1664 + c4);
  s.x *= g.x; s.y *= g.y; s.z *= g.z; s.w *= g.w;
  *(float4*)(g_a + row * 512 + c4) = s;
}

// ---------------------------------------------------------------------------
// Output GEMM: out[256,1024] = g_a[256,512] @ Wo[512,1024]
// 16x64 tiles -> grid (16,16) = 256 CTAs. k-depth 32, double-buffered.
// ---------------------------------------------------------------------------
__global__ __launch_bounds__(256) void out_gemm_kernel(
    const float* __restrict__ Wo, float* __restrict__ out) {
  __shared__ float As[2][32][16];
  __shared__ float Bs[2][32][64];

  const int colBase = blockIdx.x * 64;  // 0..1023
  const int rowBase = blockIdx.y * 16;  // 0..255

  const int tid = threadIdx.x;
  const int ty = tid >> 4, tx = tid & 15;
  const int lrA = tid >> 3, kgA = tid & 7;
  const int lkB = tid >> 4, c4B = (tid & 15) << 2;

  u64 acc0 = 0ULL, acc1 = 0ULL;

  const int NIT = 512 / 32;
  float4 av, bv0, bv1;
  if (tid < 128) av = *(const float4*)(g_a + (rowBase + lrA) * 512 + kgA * 4);
  bv0 = *(const float4*)(Wo + lkB * DD + colBase + c4B);
  bv1 = *(const float4*)(Wo + (lkB + 16) * DD + colBase + c4B);
  if (tid < 128) {
    As[0][kgA * 4 + 0][lrA] = av.x;
    As[0][kgA * 4 + 1][lrA] = av.y;
    As[0][kgA * 4 + 2][lrA] = av.z;
    As[0][kgA * 4 + 3][lrA] = av.w;
  }
  *(float4*)(&Bs[0][lkB][c4B]) = bv0;
  *(float4*)(&Bs[0][lkB + 16][c4B]) = bv1;
  __syncthreads();

  int cur = 0;
  for (int i = 0; i < NIT; i++) {
    if (i + 1 < NIT) {
      int kb = (i + 1) * 32;
      if (tid < 128) av = *(const float4*)(g_a + (rowBase + lrA) * 512 + kb + kgA * 4);
      bv0 = *(const float4*)(Wo + (kb + lkB) * DD + colBase + c4B);
      bv1 = *(const float4*)(Wo + (kb + lkB + 16) * DD + colBase + c4B);
    }
#pragma unroll
    for (int kk = 0; kk < 32; kk++) {
      float a = As[cur][kk][ty];
      F4U bb; bb.f = *(float4*)(&Bs[cur][kk][tx * 4]);
      u64 a2 = pack2(a, a);
      acc0 = fma2(a2, bb.u[0], acc0);
      acc1 = fma2(a2, bb.u[1], acc1);
    }
    if (i + 1 < NIT) {
      int nxt = cur ^ 1;
      if (tid < 128) {
        As[nxt][kgA * 4 + 0][lrA] = av.x;
        As[nxt][kgA * 4 + 1][lrA] = av.y;
        As[nxt][kgA * 4 + 2][lrA] = av.z;
        As[nxt][kgA * 4 + 3][lrA] = av.w;
      }
      *(float4*)(&Bs[nxt][lkB][c4B]) = bv0;
      *(float4*)(&Bs[nxt][lkB + 16][c4B]) = bv1;
      __syncthreads();
      cur = nxt;
    }
  }

  F4U o; o.u[0] = acc0; o.u[1] = acc1;
  *(float4*)(out + (rowBase + ty) * DD + colBase + tx * 4) = o.f;
}

// ---------------------------------------------------------------------------
// Entry point
// ---------------------------------------------------------------------------
extern "C" void kernel_launch(void* const* d_in, const int* in_sizes, int n_in,
                              void* d_out, int out_size) {
  const float* x    = (const float*)d_in[0];
  const float* Wq   = (const float*)d_in[1];
  const float* Wk   = (const float*)d_in[2];
  const float* Wv   = (const float*)d_in[3];
  const float* Wb   = (const float*)d_in[4];
  const float* Wtg  = (const float*)d_in[5];
  const float* ml   = (const float*)d_in[6];
  const float* ldc  = (const float*)d_in[7];
  const float* oms  = (const float*)d_in[8];
  const float* Wg   = (const float*)d_in[9];
  const float* Wo   = (const float*)d_in[10];
  float* out = (float*)d_out;

  proj_gemm_kernel<<<dim3(NPROJ / 64, NROWS / 16), 256>>>(x, Wq, Wk, Wv, Wb, Wtg, Wg);
  scan_kernel<<<BB * HH * RRm, 256>>>(ml, ldc, oms);
  reduce_y_kernel<<<(NROWS * 512 / 4 + 255) / 256, 256>>>();
  out_gemm_kernel<<<dim3(DD / 64, NROWS / 16), 256>>>(Wo, out);
}

// round 6
// speedup vs baseline: 1.2807x; 1.2807x over previous
#include <cuda_runtime.h>
#include <math.h>

// Problem constants
#define BB 2
#define TT 128
#define DD 1024
#define HH 8
#define RRm 8
#define DK 64
#define DV 64
#define NPROJ 2176           // 512 q | 512 k | 512 v | 64 beta | 64 tg | 512 g
#define NROWS 256            // B*T

typedef unsigned long long u64;

// Scratch (no allocations allowed)
__device__ __align__(16) float g_proj[NROWS * NPROJ];          // 2.2 MB
__device__ __align__(16) float g_yr[RRm * NROWS * 512];        // 4 MB  (per-r mode reads)
__device__ __align__(16) float g_a[NROWS * 512];               // 512 KB (gated, r-reduced)

// ---------------------------------------------------------------------------
// f32x2 helpers (ptxas never emits FFMA2 from C++; PTX only)
// ---------------------------------------------------------------------------
__device__ __forceinline__ u64 pack2(float lo, float hi) {
  u64 r; asm("mov.b64 %0, {%1, %2};" : "=l"(r) : "f"(lo), "f"(hi)); return r;
}
__device__ __forceinline__ void unpack2(u64 v, float& lo, float& hi) {
  asm("mov.b64 {%0, %1}, %2;" : "=f"(lo), "=f"(hi) : "l"(v));
}
__device__ __forceinline__ u64 fma2(u64 a, u64 b, u64 c) {
  u64 d; asm("fma.rn.f32x2 %0, %1, %2, %3;" : "=l"(d) : "l"(a), "l"(b), "l"(c)); return d;
}
__device__ __forceinline__ u64 mul2(u64 a, u64 b) {
  u64 d; asm("mul.rn.f32x2 %0, %1, %2;" : "=l"(d) : "l"(a), "l"(b)); return d;
}
__device__ __forceinline__ u64 neg2(u64 a) { return a ^ 0x8000000080000000ULL; }

union F4U { float4 f; u64 u[2]; };

__device__ __forceinline__ float sigmoidf_(float x) { return 1.f / (1.f + expf(-x)); }

// ===========================================================================
// GEMM body: 64x64 tile, 128 threads, 4 rows x 8 cols per thread,
// k-depth 16, double-buffered smem, register prefetch.
// Per kk: 1 LDS.128 (A) + 2 LDS.128 (B) + 16 FFMA2.
// As rows padded to 68 to avoid bank conflicts on float4 column reads.
// ===========================================================================

// ---------------------------------------------------------------------------
// Fused projection GEMM: proj[256, 2176] = x @ [Wq|Wk|Wv|Wb|Wtg|Wg]
// grid (34, 4) = 136 CTAs. Sigmoid for cols >= 1536.
// ---------------------------------------------------------------------------
__global__ __launch_bounds__(128) void proj_gemm_kernel(
    const float* __restrict__ x,
    const float* __restrict__ Wq, const float* __restrict__ Wk,
    const float* __restrict__ Wv, const float* __restrict__ Wb,
    const float* __restrict__ Wtg, const float* __restrict__ Wg) {
  __shared__ float As[2][16][68];
  __shared__ float Bs[2][16][64];

  const int colBase = blockIdx.x * 64;
  const int rowBase = blockIdx.y * 64;

  const float* W; int lc, ldw;
  if (colBase < 512)       { W = Wq;  lc = colBase;        ldw = 512; }
  else if (colBase < 1024) { W = Wk;  lc = colBase - 512;  ldw = 512; }
  else if (colBase < 1536) { W = Wv;  lc = colBase - 1024; ldw = 512; }
  else if (colBase < 1600) { W = Wb;  lc = colBase - 1536; ldw = 64;  }
  else if (colBase < 1664) { W = Wtg; lc = colBase - 1600; ldw = 64;  }
  else                     { W = Wg;  lc = colBase - 1664; ldw = 512; }

  const int tid = threadIdx.x;
  const int rg = tid >> 3;              // 0..15 -> rows rg*4..+3
  const int cg = tid & 7;               // 0..7  -> cols cg*8..+7
  const int lrA = tid >> 1, kgA = (tid & 1) * 8;   // A: row lrA, k kgA..kgA+7
  const int lkB = tid >> 3, c8B = (tid & 7) * 8;   // B: k lkB, cols c8B..+7

  u64 acc[4][4];
#pragma unroll
  for (int i = 0; i < 4; i++)
#pragma unroll
    for (int j = 0; j < 4; j++) acc[i][j] = 0ULL;

  const int NIT = DD / 16;
  float4 a0, a1, b0, b1;
  {
    const float* xr = x + (rowBase + lrA) * DD + kgA;
    a0 = *(const float4*)(xr);
    a1 = *(const float4*)(xr + 4);
    const float* wr = W + lkB * ldw + lc + c8B;
    b0 = *(const float4*)(wr);
    b1 = *(const float4*)(wr + 4);
  }
  As[0][kgA + 0][lrA] = a0.x; As[0][kgA + 1][lrA] = a0.y;
  As[0][kgA + 2][lrA] = a0.z; As[0][kgA + 3][lrA] = a0.w;
  As[0][kgA + 4][lrA] = a1.x; As[0][kgA + 5][lrA] = a1.y;
  As[0][kgA + 6][lrA] = a1.z; As[0][kgA + 7][lrA] = a1.w;
  *(float4*)(&Bs[0][lkB][c8B]) = b0;
  *(float4*)(&Bs[0][lkB][c8B + 4]) = b1;
  __syncthreads();

  int cur = 0;
  for (int i = 0; i < NIT; i++) {
    if (i + 1 < NIT) {
      int kb = (i + 1) * 16;
      const float* xr = x + (rowBase + lrA) * DD + kb + kgA;
      a0 = *(const float4*)(xr);
      a1 = *(const float4*)(xr + 4);
      const float* wr = W + (kb + lkB) * ldw + lc + c8B;
      b0 = *(const float4*)(wr);
      b1 = *(const float4*)(wr + 4);
    }
#pragma unroll
    for (int kk = 0; kk < 16; kk++) {
      float4 a = *(float4*)(&As[cur][kk][rg * 4]);
      F4U bb0; bb0.f = *(float4*)(&Bs[cur][kk][cg * 8]);
      F4U bb1; bb1.f = *(float4*)(&Bs[cur][kk][cg * 8 + 4]);
      u64 ar[4];
      ar[0] = pack2(a.x, a.x); ar[1] = pack2(a.y, a.y);
      ar[2] = pack2(a.z, a.z); ar[3] = pack2(a.w, a.w);
#pragma unroll
      for (int j = 0; j < 4; j++) {
        acc[j][0] = fma2(ar[j], bb0.u[0], acc[j][0]);
        acc[j][1] = fma2(ar[j], bb0.u[1], acc[j][1]);
        acc[j][2] = fma2(ar[j], bb1.u[0], acc[j][2]);
        acc[j][3] = fma2(ar[j], bb1.u[1], acc[j][3]);
      }
    }
    if (i + 1 < NIT) {
      int nxt = cur ^ 1;
      As[nxt][kgA + 0][lrA] = a0.x; As[nxt][kgA + 1][lrA] = a0.y;
      As[nxt][kgA + 2][lrA] = a0.z; As[nxt][kgA + 3][lrA] = a0.w;
      As[nxt][kgA + 4][lrA] = a1.x; As[nxt][kgA + 5][lrA] = a1.y;
      As[nxt][kgA + 6][lrA] = a1.z; As[nxt][kgA + 7][lrA] = a1.w;
      *(float4*)(&Bs[nxt][lkB][c8B]) = b0;
      *(float4*)(&Bs[nxt][lkB][c8B + 4]) = b1;
      __syncthreads();
      cur = nxt;
    }
  }

  const bool sig = (colBase >= 1536);
#pragma unroll
  for (int j = 0; j < 4; j++) {
    F4U o0, o1;
    o0.u[0] = acc[j][0]; o0.u[1] = acc[j][1];
    o1.u[0] = acc[j][2]; o1.u[1] = acc[j][3];
    if (sig) {
      o0.f.x = sigmoidf_(o0.f.x); o0.f.y = sigmoidf_(o0.f.y);
      o0.f.z = sigmoidf_(o0.f.z); o0.f.w = sigmoidf_(o0.f.w);
      o1.f.x = sigmoidf_(o1.f.x); o1.f.y = sigmoidf_(o1.f.y);
      o1.f.z = sigmoidf_(o1.f.z); o1.f.w = sigmoidf_(o1.f.w);
    }
    float* orow = g_proj + (rowBase + rg * 4 + j) * NPROJ + colBase + cg * 8;
    *(float4*)(orow) = o0.f;
    *(float4*)(orow + 4) = o1.f;
  }
}

// ---------------------------------------------------------------------------
// Sequential scan. One CTA per (b,h,r) chain: 128 CTAs, 256 threads.
// Thread owns v = tid/4 (row), k-slice [16*(tid%4), +16) as 8 f32x2 pairs.
// Register prefetch of t+1's q/k/v/beta/tg hides L2 latency.
// ---------------------------------------------------------------------------
__global__ __launch_bounds__(256) void scan_kernel(
    const float* __restrict__ mode_logits,
    const float* __restrict__ log_decay,
    const float* __restrict__ omega_log_scale) {
  const int cid = blockIdx.x;        // 0..127
  const int b = cid >> 6;
  const int h = (cid >> 3) & 7;
  const int r = cid & 7;
  const int tid = threadIdx.x;
  const int v = tid >> 2;
  const int q4 = tid & 3;
  const int k0 = q4 * 16;

  // mode weight: softmax over R for this head
  float ml[RRm];
  float mx = -1e30f;
#pragma unroll
  for (int i = 0; i < RRm; i++) { ml[i] = mode_logits[h * RRm + i]; mx = fmaxf(mx, ml[i]); }
  float ssum = 0.f;
#pragma unroll
  for (int i = 0; i < RRm; i++) ssum += expf(ml[i] - mx);
  const float mw = expf(ml[r] - mx) / ssum;

  // rho = exp(-softplus(log_decay))
  const float ldv = log_decay[h * RRm + r];
  const float sp = (ldv > 20.f) ? ldv : log1pf(expf(ldv));
  const float rho = expf(-sp);
  const float osc = expf(omega_log_scale[h * RRm + r]);

  u64 cw2[8], sw2[8], sr2[8], si2[8];
  const float c_ln = 9.210340371976184f / 64.f;  // ln(10000)/64
#pragma unroll
  for (int p = 0; p < 8; p++) {
    float pv = (float)(k0 + 2 * p);              // even -> (k & ~1) identical for pair
    float om = osc * expf(-pv * c_ln);
    float c = cosf(om), s = sinf(om);
    cw2[p] = pack2(c, c);
    sw2[p] = pack2(s, s);
    sr2[p] = 0ULL;
    si2[p] = 0ULL;
  }

  const int qoff = h * DK + k0;
  const float* rowBase = g_proj + (b * TT) * NPROJ;
  float* ybase = g_yr + r * (NROWS * 512) + (b * TT) * 512 + h * DV + v;

  // Prefetch t = 0
  F4U kbuf[4], qbuf[4];
  float vn, betan, tgn;
#pragma unroll
  for (int g4 = 0; g4 < 4; g4++) {
    kbuf[g4].f = *(const float4*)(rowBase + 512 + qoff + g4 * 4);
    qbuf[g4].f = *(const float4*)(rowBase + qoff + g4 * 4);
  }
  vn    = rowBase[1024 + h * DV + v];
  betan = rowBase[1536 + h * RRm + r];
  tgn   = rowBase[1600 + h * RRm + r];

  for (int t = 0; t < TT; t++) {
    u64 kt2[8], qt2[8];
#pragma unroll
    for (int g4 = 0; g4 < 4; g4++) {
      kt2[g4 * 2 + 0] = kbuf[g4].u[0]; kt2[g4 * 2 + 1] = kbuf[g4].u[1];
      qt2[g4 * 2 + 0] = qbuf[g4].u[0]; qt2[g4 * 2 + 1] = qbuf[g4].u[1];
    }
    const float vtv = vn, beta = betan, tg = tgn;

    // Prefetch t+1 (independent of state -> hides L2 latency)
    if (t + 1 < TT) {
      const float* row = rowBase + (t + 1) * NPROJ;
#pragma unroll
      for (int g4 = 0; g4 < 4; g4++) {
        kbuf[g4].f = *(const float4*)(row + 512 + qoff + g4 * 4);
        qbuf[g4].f = *(const float4*)(row + qoff + g4 * 4);
      }
      vn    = row[1024 + h * DV + v];
      betan = row[1536 + h * RRm + r];
      tgn   = row[1600 + h * RRm + r];
    }

    const float decay = tg * rho;
    const u64 decay2 = pack2(decay, decay);

    // rotate state (complex mult by decay * e^{i omega}) + pred partial
    u64 predA = 0ULL, predB = 0ULL;
#pragma unroll
    for (int p = 0; p < 8; p++) {
      u64 dc = mul2(decay2, cw2[p]);
      u64 ds = mul2(decay2, sw2[p]);
      u64 m1 = mul2(ds, si2[p]);
      u64 rr = fma2(dc, sr2[p], neg2(m1));
      u64 m2 = mul2(dc, si2[p]);
      si2[p] = fma2(ds, sr2[p], m2);
      sr2[p] = rr;                       // sr temporarily holds rot_r
      if (p & 1) predB = fma2(rr, kt2[p], predB);
      else       predA = fma2(rr, kt2[p], predA);
    }
    u64 pred2; {
      float alo, ahi, blo, bhi;
      unpack2(predA, alo, ahi); unpack2(predB, blo, bhi);
      pred2 = pack2(alo + blo, ahi + bhi);
    }
    float plo, phi; unpack2(pred2, plo, phi);
    float pred = plo + phi;
    pred += __shfl_xor_sync(0xffffffffu, pred, 1);
    pred += __shfl_xor_sync(0xffffffffu, pred, 2);

    const float w = beta * (vtv - pred);
    const u64 w2 = pack2(w, w);

    u64 rdA = 0ULL, rdB = 0ULL;
#pragma unroll
    for (int p = 0; p < 8; p++) {
      sr2[p] = fma2(w2, kt2[p], sr2[p]); // sr_new = rot_r + beta*err*k
      if (p & 1) rdB = fma2(sr2[p], qt2[p], rdB);
      else       rdA = fma2(sr2[p], qt2[p], rdA);
    }
    float r0lo, r0hi, r1lo, r1hi;
    unpack2(rdA, r0lo, r0hi); unpack2(rdB, r1lo, r1hi);
    float rd = (r0lo + r1lo) + (r0hi + r1hi);
    rd += __shfl_xor_sync(0xffffffffu, rd, 1);
    rd += __shfl_xor_sync(0xffffffffu, rd, 2);

    if (q4 == 0) ybase[t * 512] = mw * rd;
  }
}

// ---------------------------------------------------------------------------
// Reduce over r + apply gate: g_a[row][c] = gate[row][c] * sum_r g_yr[r][row][c]
// ---------------------------------------------------------------------------
__global__ __launch_bounds__(256) void reduce_y_kernel() {
  int idx = blockIdx.x * blockDim.x + threadIdx.x;   // float4 index
  if (idx >= NROWS * 512 / 4) return;
  int row = idx >> 7;           // 128 float4 per row
  int c4 = (idx & 127) << 2;
  float4 s = *(const float4*)(g_yr + row * 512 + c4);
#pragma unroll
  for (int r = 1; r < RRm; r++) {
    float4 t = *(const float4*)(g_yr + r * (NROWS * 512) + row * 512 + c4);
    s.x += t.x; s.y += t.y; s.z += t.z; s.w += t.w;
  }
  float4 g = *(const float4*)(g_proj + row * NPROJ + 1664 + c4);
  s.x *= g.x; s.y *= g.y; s.z *= g.z; s.w *= g.w;
  *(float4*)(g_a + row * 512 + c4) = s;
}

// ---------------------------------------------------------------------------
// Output GEMM: out[256,1024] = g_a[256,512] @ Wo[512,1024]
// 64x64 tiles -> grid (16,4) = 64 CTAs, 128 threads, 4x8 microtile.
// ---------------------------------------------------------------------------
__global__ __launch_bounds__(128) void out_gemm_kernel(
    const float* __restrict__ Wo, float* __restrict__ out) {
  __shared__ float As[2][16][68];
  __shared__ float Bs[2][16][64];

  const int colBase = blockIdx.x * 64;  // 0..1023
  const int rowBase = blockIdx.y * 64;  // 0..255

  const int tid = threadIdx.x;
  const int rg = tid >> 3;
  const int cg = tid & 7;
  const int lrA = tid >> 1, kgA = (tid & 1) * 8;
  const int lkB = tid >> 3, c8B = (tid & 7) * 8;

  u64 acc[4][4];
#pragma unroll
  for (int i = 0; i < 4; i++)
#pragma unroll
    for (int j = 0; j < 4; j++) acc[i][j] = 0ULL;

  const int NIT = 512 / 16;
  float4 a0, a1, b0, b1;
  {
    const float* ar = g_a + (rowBase + lrA) * 512 + kgA;
    a0 = *(const float4*)(ar);
    a1 = *(const float4*)(ar + 4);
    const float* wr = Wo + lkB * DD + colBase + c8B;
    b0 = *(const float4*)(wr);
    b1 = *(const float4*)(wr + 4);
  }
  As[0][kgA + 0][lrA] = a0.x; As[0][kgA + 1][lrA] = a0.y;
  As[0][kgA + 2][lrA] = a0.z; As[0][kgA + 3][lrA] = a0.w;
  As[0][kgA + 4][lrA] = a1.x; As[0][kgA + 5][lrA] = a1.y;
  As[0][kgA + 6][lrA] = a1.z; As[0][kgA + 7][lrA] = a1.w;
  *(float4*)(&Bs[0][lkB][c8B]) = b0;
  *(float4*)(&Bs[0][lkB][c8B + 4]) = b1;
  __syncthreads();

  int cur = 0;
  for (int i = 0; i < NIT; i++) {
    if (i + 1 < NIT) {
      int kb = (i + 1) * 16;
      const float* ar = g_a + (rowBase + lrA) * 512 + kb + kgA;
      a0 = *(const float4*)(ar);
      a1 = *(const float4*)(ar + 4);
      const float* wr = Wo + (kb + lkB) * DD + colBase + c8B;
      b0 = *(const float4*)(wr);
      b1 = *(const float4*)(wr + 4);
    }
#pragma unroll
    for (int kk = 0; kk < 16; kk++) {
      float4 a = *(float4*)(&As[cur][kk][rg * 4]);
      F4U bb0; bb0.f = *(float4*)(&Bs[cur][kk][cg * 8]);
      F4U bb1; bb1.f = *(float4*)(&Bs[cur][kk][cg * 8 + 4]);
      u64 ar2[4];
      ar2[0] = pack2(a.x, a.x); ar2[1] = pack2(a.y, a.y);
      ar2[2] = pack2(a.z, a.z); ar2[3] = pack2(a.w, a.w);
#pragma unroll
      for (int j = 0; j < 4; j++) {
        acc[j][0] = fma2(ar2[j], bb0.u[0], acc[j][0]);
        acc[j][1] = fma2(ar2[j], bb0.u[1], acc[j][1]);
        acc[j][2] = fma2(ar2[j], bb1.u[0], acc[j][2]);
        acc[j][3] = fma2(ar2[j], bb1.u[1], acc[j][3]);
      }
    }
    if (i + 1 < NIT) {
      int nxt = cur ^ 1;
      As[nxt][kgA + 0][lrA] = a0.x; As[nxt][kgA + 1][lrA] = a0.y;
      As[nxt][kgA + 2][lrA] = a0.z; As[nxt][kgA + 3][lrA] = a0.w;
      As[nxt][kgA + 4][lrA] = a1.x; As[nxt][kgA + 5][lrA] = a1.y;
      As[nxt][kgA + 6][lrA] = a1.z; As[nxt][kgA + 7][lrA] = a1.w;
      *(float4*)(&Bs[nxt][lkB][c8B]) = b0;
      *(float4*)(&Bs[nxt][lkB][c8B + 4]) = b1;
      __syncthreads();
      cur = nxt;
    }
  }

#pragma unroll
  for (int j = 0; j < 4; j++) {
    F4U o0, o1;
    o0.u[0] = acc[j][0]; o0.u[1] = acc[j][1];
    o1.u[0] = acc[j][2]; o1.u[1] = acc[j][3];
    float* orow = out + (rowBase + rg * 4 + j) * DD + colBase + cg * 8;
    *(float4*)(orow) = o0.f;
    *(float4*)(orow + 4) = o1.f;
  }
}

// ---------------------------------------------------------------------------
// Entry point
// ---------------------------------------------------------------------------
extern "C" void kernel_launch(void* const* d_in, const int* in_sizes, int n_in,
                              void* d_out, int out_size) {
  const float* x    = (const float*)d_in[0];
  const float* Wq   = (const float*)d_in[1];
  const float* Wk   = (const float*)d_in[2];
  const float* Wv   = (const float*)d_in[3];
  const float* Wb   = (const float*)d_in[4];
  const float* Wtg  = (const float*)d_in[5];
  const float* ml   = (const float*)d_in[6];
  const float* ldc  = (const float*)d_in[7];
  const float* oms  = (const float*)d_in[8];
  const float* Wg   = (const float*)d_in[9];
  const float* Wo   = (const float*)d_in[10];
  float* out = (float*)d_out;

  proj_gemm_kernel<<<dim3(NPROJ / 64, NROWS / 64), 128>>>(x, Wq, Wk, Wv, Wb, Wtg, Wg);
  scan_kernel<<<BB * HH * RRm, 256>>>(ml, ldc, oms);
  reduce_y_kernel<<<(NROWS * 512 / 4 + 255) / 256, 256>>>();
  out_gemm_kernel<<<dim3(DD / 64, NROWS / 64), 128>>>(Wo, out);
}

// round 7
// speedup vs baseline: 1.8063x; 1.4103x over previous
#include <cuda_runtime.h>
#include <math.h>

// Problem constants
#define BB 2
#define TT 128
#define DD 1024
#define HH 8
#define RRm 8
#define DK 64
#define DV 64
#define NPROJ 2176           // 512 q | 512 k | 512 v | 64 beta | 64 tg | 512 g
#define NROWS 256            // B*T
#define CH 16                // scan chunk (timesteps staged in smem)

typedef unsigned long long u64;

// Scratch (no allocations allowed)
__device__ __align__(16) float g_proj[NROWS * NPROJ];          // 2.2 MB
__device__ __align__(16) float g_yr[RRm * NROWS * 512];        // 4 MB  (per-r mode reads)
__device__ __align__(16) float g_a[NROWS * 512];               // 512 KB (gated, r-reduced)

// ---------------------------------------------------------------------------
// f32x2 helpers (ptxas never emits FFMA2 from C++; PTX only)
// ---------------------------------------------------------------------------
__device__ __forceinline__ u64 pack2(float lo, float hi) {
  u64 r; asm("mov.b64 %0, {%1, %2};" : "=l"(r) : "f"(lo), "f"(hi)); return r;
}
__device__ __forceinline__ void unpack2(u64 v, float& lo, float& hi) {
  asm("mov.b64 {%0, %1}, %2;" : "=f"(lo), "=f"(hi) : "l"(v));
}
__device__ __forceinline__ u64 fma2(u64 a, u64 b, u64 c) {
  u64 d; asm("fma.rn.f32x2 %0, %1, %2, %3;" : "=l"(d) : "l"(a), "l"(b), "l"(c)); return d;
}
__device__ __forceinline__ u64 mul2(u64 a, u64 b) {
  u64 d; asm("mul.rn.f32x2 %0, %1, %2;" : "=l"(d) : "l"(a), "l"(b)); return d;
}
__device__ __forceinline__ u64 neg2(u64 a) { return a ^ 0x8000000080000000ULL; }

union F4U { float4 f; u64 u[2]; };

__device__ __forceinline__ float sigmoidf_(float x) { return 1.f / (1.f + expf(-x)); }

// ===========================================================================
// GEMM body: 64x64 tile, 256 threads (2 warps/SMSP), 4x4 microtile,
// k-depth 16, double-buffered smem, register prefetch.
// Per kk per thread: 1 LDS.128 (A) + 1 LDS.128 (B) + 8 FFMA2.
// ===========================================================================

// ---------------------------------------------------------------------------
// Fused projection GEMM: proj[256, 2176] = x @ [Wq|Wk|Wv|Wb|Wtg|Wg]
// grid (34, 4) = 136 CTAs. Sigmoid for cols >= 1536.
// ---------------------------------------------------------------------------
__global__ __launch_bounds__(256) void proj_gemm_kernel(
    const float* __restrict__ x,
    const float* __restrict__ Wq, const float* __restrict__ Wk,
    const float* __restrict__ Wv, const float* __restrict__ Wb,
    const float* __restrict__ Wtg, const float* __restrict__ Wg) {
  __shared__ float As[2][16][68];
  __shared__ float Bs[2][16][64];

  const int colBase = blockIdx.x * 64;
  const int rowBase = blockIdx.y * 64;

  const float* W; int lc, ldw;
  if (colBase < 512)       { W = Wq;  lc = colBase;        ldw = 512; }
  else if (colBase < 1024) { W = Wk;  lc = colBase - 512;  ldw = 512; }
  else if (colBase < 1536) { W = Wv;  lc = colBase - 1024; ldw = 512; }
  else if (colBase < 1600) { W = Wb;  lc = colBase - 1536; ldw = 64;  }
  else if (colBase < 1664) { W = Wtg; lc = colBase - 1600; ldw = 64;  }
  else                     { W = Wg;  lc = colBase - 1664; ldw = 512; }

  const int tid = threadIdx.x;
  const int ty = tid >> 4, tx = tid & 15;           // compute: rows ty*4+, cols tx*4+
  const int lrA = tid >> 2, kgA = (tid & 3) * 4;    // A: row lrA, k kgA..+3
  const int lkB = tid >> 4, c4B = (tid & 15) << 2;  // B: k lkB, cols c4B..+3

  u64 acc[4][2];
#pragma unroll
  for (int i = 0; i < 4; i++) { acc[i][0] = 0ULL; acc[i][1] = 0ULL; }

  const int NIT = DD / 16;
  float4 av, bv;
  av = *(const float4*)(x + (rowBase + lrA) * DD + kgA);
  bv = *(const float4*)(W + lkB * ldw + lc + c4B);
  As[0][kgA + 0][lrA] = av.x; As[0][kgA + 1][lrA] = av.y;
  As[0][kgA + 2][lrA] = av.z; As[0][kgA + 3][lrA] = av.w;
  *(float4*)(&Bs[0][lkB][c4B]) = bv;
  __syncthreads();

  int cur = 0;
  for (int i = 0; i < NIT; i++) {
    if (i + 1 < NIT) {
      int kb = (i + 1) * 16;
      av = *(const float4*)(x + (rowBase + lrA) * DD + kb + kgA);
      bv = *(const float4*)(W + (kb + lkB) * ldw + lc + c4B);
    }
#pragma unroll
    for (int kk = 0; kk < 16; kk++) {
      float4 a = *(float4*)(&As[cur][kk][ty * 4]);
      F4U bb; bb.f = *(float4*)(&Bs[cur][kk][tx * 4]);
      u64 a0 = pack2(a.x, a.x);
      u64 a1 = pack2(a.y, a.y);
      u64 a2 = pack2(a.z, a.z);
      u64 a3 = pack2(a.w, a.w);
      acc[0][0] = fma2(a0, bb.u[0], acc[0][0]);
      acc[0][1] = fma2(a0, bb.u[1], acc[0][1]);
      acc[1][0] = fma2(a1, bb.u[0], acc[1][0]);
      acc[1][1] = fma2(a1, bb.u[1], acc[1][1]);
      acc[2][0] = fma2(a2, bb.u[0], acc[2][0]);
      acc[2][1] = fma2(a2, bb.u[1], acc[2][1]);
      acc[3][0] = fma2(a3, bb.u[0], acc[3][0]);
      acc[3][1] = fma2(a3, bb.u[1], acc[3][1]);
    }
    if (i + 1 < NIT) {
      int nxt = cur ^ 1;
      As[nxt][kgA + 0][lrA] = av.x; As[nxt][kgA + 1][lrA] = av.y;
      As[nxt][kgA + 2][lrA] = av.z; As[nxt][kgA + 3][lrA] = av.w;
      *(float4*)(&Bs[nxt][lkB][c4B]) = bv;
      __syncthreads();
      cur = nxt;
    }
  }

  const bool sig = (colBase >= 1536);
#pragma unroll
  for (int j = 0; j < 4; j++) {
    F4U o; o.u[0] = acc[j][0]; o.u[1] = acc[j][1];
    if (sig) {
      o.f.x = sigmoidf_(o.f.x); o.f.y = sigmoidf_(o.f.y);
      o.f.z = sigmoidf_(o.f.z); o.f.w = sigmoidf_(o.f.w);
    }
    *(float4*)(g_proj + (rowBase + ty * 4 + j) * NPROJ + colBase + tx * 4) = o.f;
  }
}

// ---------------------------------------------------------------------------
// Sequential scan. One CTA per (b,h,r) chain: 128 CTAs, 256 threads.
// q/k/v/beta/tg for CH=16 steps staged in smem (double-buffered, one sync
// per chunk). Per-step data reads are broadcast LDS instead of redundant LDG.
// Thread owns v = tid/4 (row), k-slice [16*(tid%4), +16) as 8 f32x2 pairs.
// ---------------------------------------------------------------------------
__global__ __launch_bounds__(256) void scan_kernel(
    const float* __restrict__ mode_logits,
    const float* __restrict__ log_decay,
    const float* __restrict__ omega_log_scale) {
  __shared__ float sQ[2][CH][64];
  __shared__ float sK[2][CH][64];
  __shared__ float sV[2][CH][64];
  __shared__ float sB[2][CH];
  __shared__ float sT[2][CH];

  const int cid = blockIdx.x;        // 0..127
  const int b = cid >> 6;
  const int h = (cid >> 3) & 7;
  const int r = cid & 7;
  const int tid = threadIdx.x;
  const int v = tid >> 2;
  const int q4 = tid & 3;
  const int k0 = q4 * 16;

  // mode weight: softmax over R for this head
  float ml[RRm];
  float mx = -1e30f;
#pragma unroll
  for (int i = 0; i < RRm; i++) { ml[i] = mode_logits[h * RRm + i]; mx = fmaxf(mx, ml[i]); }
  float ssum = 0.f;
#pragma unroll
  for (int i = 0; i < RRm; i++) ssum += expf(ml[i] - mx);
  const float mw = expf(ml[r] - mx) / ssum;

  // rho = exp(-softplus(log_decay))
  const float ldv = log_decay[h * RRm + r];
  const float sp = (ldv > 20.f) ? ldv : log1pf(expf(ldv));
  const float rho = expf(-sp);
  const float osc = expf(omega_log_scale[h * RRm + r]);

  u64 cw2[8], sw2[8], sr2[8], si2[8];
  const float c_ln = 9.210340371976184f / 64.f;  // ln(10000)/64
#pragma unroll
  for (int p = 0; p < 8; p++) {
    float pv = (float)(k0 + 2 * p);              // even -> (k & ~1) identical for pair
    float om = osc * expf(-pv * c_ln);
    float c = cosf(om), s = sinf(om);
    cw2[p] = pack2(c, c);
    sw2[p] = pack2(s, s);
    sr2[p] = 0ULL;
    si2[p] = 0ULL;
  }

  // Cooperative chunk loading: thread -> (step ls, float4 part lp)
  const int ls = tid >> 4;       // 0..15
  const int lp = tid & 15;       // 0..15
  const float* gpb = g_proj + (b * TT) * NPROJ;   // batch base
  float* ybase = g_yr + r * (NROWS * 512) + (b * TT) * 512 + h * DV + v;

  float4 qf, kf, vf;
  float bf = 0.f, tf = 0.f;
  {
    const float* row = gpb + ls * NPROJ + h * 64;
    qf = *(const float4*)(row + lp * 4);
    kf = *(const float4*)(row + 512 + lp * 4);
    vf = *(const float4*)(row + 1024 + lp * 4);
    if (lp == 0) bf = gpb[ls * NPROJ + 1536 + h * RRm + r];
    if (lp == 1) tf = gpb[ls * NPROJ + 1600 + h * RRm + r];
  }
  *(float4*)(&sQ[0][ls][lp * 4]) = qf;
  *(float4*)(&sK[0][ls][lp * 4]) = kf;
  *(float4*)(&sV[0][ls][lp * 4]) = vf;
  if (lp == 0) sB[0][ls] = bf;
  if (lp == 1) sT[0][ls] = tf;
  __syncthreads();

  const int NCH = TT / CH;
  int cur = 0;
  for (int c = 0; c < NCH; c++) {
    // Prefetch next chunk into registers (overlaps with the 16-step compute)
    if (c + 1 < NCH) {
      const float* row = gpb + ((c + 1) * CH + ls) * NPROJ + h * 64;
      qf = *(const float4*)(row + lp * 4);
      kf = *(const float4*)(row + 512 + lp * 4);
      vf = *(const float4*)(row + 1024 + lp * 4);
      if (lp == 0) bf = gpb[((c + 1) * CH + ls) * NPROJ + 1536 + h * RRm + r];
      if (lp == 1) tf = gpb[((c + 1) * CH + ls) * NPROJ + 1600 + h * RRm + r];
    }

    for (int tt = 0; tt < CH; tt++) {
      u64 kt2[8], qt2[8];
#pragma unroll
      for (int g4 = 0; g4 < 4; g4++) {
        F4U kv; kv.f = *(const float4*)(&sK[cur][tt][k0 + g4 * 4]);
        F4U qv; qv.f = *(const float4*)(&sQ[cur][tt][k0 + g4 * 4]);
        kt2[g4 * 2 + 0] = kv.u[0]; kt2[g4 * 2 + 1] = kv.u[1];
        qt2[g4 * 2 + 0] = qv.u[0]; qt2[g4 * 2 + 1] = qv.u[1];
      }
      const float vtv  = sV[cur][tt][v];
      const float beta = sB[cur][tt];
      const float tg   = sT[cur][tt];
      const float decay = tg * rho;
      const u64 decay2 = pack2(decay, decay);

      // rotate state (complex mult by decay * e^{i omega}) + pred partial
      u64 predA = 0ULL, predB = 0ULL;
#pragma unroll
      for (int p = 0; p < 8; p++) {
        u64 dc = mul2(decay2, cw2[p]);
        u64 ds = mul2(decay2, sw2[p]);
        u64 m1 = mul2(ds, si2[p]);
        u64 rr = fma2(dc, sr2[p], neg2(m1));
        u64 m2 = mul2(dc, si2[p]);
        si2[p] = fma2(ds, sr2[p], m2);
        sr2[p] = rr;                       // sr temporarily holds rot_r
        if (p & 1) predB = fma2(rr, kt2[p], predB);
        else       predA = fma2(rr, kt2[p], predA);
      }
      float alo, ahi, blo, bhi;
      unpack2(predA, alo, ahi); unpack2(predB, blo, bhi);
      float pred = (alo + blo) + (ahi + bhi);
      pred += __shfl_xor_sync(0xffffffffu, pred, 1);
      pred += __shfl_xor_sync(0xffffffffu, pred, 2);

      const float w = beta * (vtv - pred);
      const u64 w2 = pack2(w, w);

      u64 rdA = 0ULL, rdB = 0ULL;
#pragma unroll
      for (int p = 0; p < 8; p++) {
        sr2[p] = fma2(w2, kt2[p], sr2[p]); // sr_new = rot_r + beta*err*k
        if (p & 1) rdB = fma2(sr2[p], qt2[p], rdB);
        else       rdA = fma2(sr2[p], qt2[p], rdA);
      }
      float r0lo, r0hi, r1lo, r1hi;
      unpack2(rdA, r0lo, r0hi); unpack2(rdB, r1lo, r1hi);
      float rd = (r0lo + r1lo) + (r0hi + r1hi);
      rd += __shfl_xor_sync(0xffffffffu, rd, 1);
      rd += __shfl_xor_sync(0xffffffffu, rd, 2);

      if (q4 == 0) ybase[(c * CH + tt) * 512] = mw * rd;
    }

    if (c + 1 < NCH) {
      int nxt = cur ^ 1;
      *(float4*)(&sQ[nxt][ls][lp * 4]) = qf;
      *(float4*)(&sK[nxt][ls][lp * 4]) = kf;
      *(float4*)(&sV[nxt][ls][lp * 4]) = vf;
      if (lp == 0) sB[nxt][ls] = bf;
      if (lp == 1) sT[nxt][ls] = tf;
      __syncthreads();
      cur = nxt;
    }
  }
}

// ---------------------------------------------------------------------------
// Reduce over r + apply gate: g_a[row][c] = gate[row][c] * sum_r g_yr[r][row][c]
// ---------------------------------------------------------------------------
__global__ __launch_bounds__(256) void reduce_y_kernel() {
  int idx = blockIdx.x * blockDim.x + threadIdx.x;   // float4 index
  if (idx >= NROWS * 512 / 4) return;
  int row = idx >> 7;           // 128 float4 per row
  int c4 = (idx & 127) << 2;
  float4 s = *(const float4*)(g_yr + row * 512 + c4);
#pragma unroll
  for (int r = 1; r < RRm; r++) {
    float4 t = *(const float4*)(g_yr + r * (NROWS * 512) + row * 512 + c4);
    s.x += t.x; s.y += t.y; s.z += t.z; s.w += t.w;
  }
  float4 g = *(const float4*)(g_proj + row * NPROJ + 1664 + c4);
  s.x *= g.x; s.y *= g.y; s.z *= g.z; s.w *= g.w;
  *(float4*)(g_a + row * 512 + c4) = s;
}

// ---------------------------------------------------------------------------
// Output GEMM: out[256,1024] = g_a[256,512] @ Wo[512,1024]
// 64x64 tiles -> grid (16,4) = 64 CTAs, 256 threads, 4x4 microtile.
// ---------------------------------------------------------------------------
__global__ __launch_bounds__(256) void out_gemm_kernel(
    const float* __restrict__ Wo, float* __restrict__ out) {
  __shared__ float As[2][16][68];
  __shared__ float Bs[2][16][64];

  const int colBase = blockIdx.x * 64;  // 0..1023
  const int rowBase = blockIdx.y * 64;  // 0..255

  const int tid = threadIdx.x;
  const int ty = tid >> 4, tx = tid & 15;
  const int lrA = tid >> 2, kgA = (tid & 3) * 4;
  const int lkB = tid >> 4, c4B = (tid & 15) << 2;

  u64 acc[4][2];
#pragma unroll
  for (int i = 0; i < 4; i++) { acc[i][0] = 0ULL; acc[i][1] = 0ULL; }

  const int NIT = 512 / 16;
  float4 av, bv;
  av = *(const float4*)(g_a + (rowBase + lrA) * 512 + kgA);
  bv = *(const float4*)(Wo + lkB * DD + colBase + c4B);
  As[0][kgA + 0][lrA] = av.x; As[0][kgA + 1][lrA] = av.y;
  As[0][kgA + 2][lrA] = av.z; As[0][kgA + 3][lrA] = av.w;
  *(float4*)(&Bs[0][lkB][c4B]) = bv;
  __syncthreads();

  int cur = 0;
  for (int i = 0; i < NIT; i++) {
    if (i + 1 < NIT) {
      int kb = (i + 1) * 16;
      av = *(const float4*)(g_a + (rowBase + lrA) * 512 + kb + kgA);
      bv = *(const float4*)(Wo + (kb + lkB) * DD + colBase + c4B);
    }
#pragma unroll
    for (int kk = 0; kk < 16; kk++) {
      float4 a = *(float4*)(&As[cur][kk][ty * 4]);
      F4U bb; bb.f = *(float4*)(&Bs[cur][kk][tx * 4]);
      u64 a0 = pack2(a.x, a.x);
      u64 a1 = pack2(a.y, a.y);
      u64 a2 = pack2(a.z, a.z);
      u64 a3 = pack2(a.w, a.w);
      acc[0][0] = fma2(a0, bb.u[0], acc[0][0]);
      acc[0][1] = fma2(a0, bb.u[1], acc[0][1]);
      acc[1][0] = fma2(a1, bb.u[0], acc[1][0]);
      acc[1][1] = fma2(a1, bb.u[1], acc[1][1]);
      acc[2][0] = fma2(a2, bb.u[0], acc[2][0]);
      acc[2][1] = fma2(a2, bb.u[1], acc[2][1]);
      acc[3][0] = fma2(a3, bb.u[0], acc[3][0]);
      acc[3][1] = fma2(a3, bb.u[1], acc[3][1]);
    }
    if (i + 1 < NIT) {
      int nxt = cur ^ 1;
      As[nxt][kgA + 0][lrA] = av.x; As[nxt][kgA + 1][lrA] = av.y;
      As[nxt][kgA + 2][lrA] = av.z; As[nxt][kgA + 3][lrA] = av.w;
      *(float4*)(&Bs[nxt][lkB][c4B]) = bv;
      __syncthreads();
      cur = nxt;
    }
  }

#pragma unroll
  for (int j = 0; j < 4; j++) {
    F4U o; o.u[0] = acc[j][0]; o.u[1] = acc[j][1];
    *(float4*)(out + (rowBase + ty * 4 + j) * DD + colBase + tx * 4) = o.f;
  }
}

// ---------------------------------------------------------------------------
// Entry point
// ---------------------------------------------------------------------------
extern "C" void kernel_launch(void* const* d_in, const int* in_sizes, int n_in,
                              void* d_out, int out_size) {
  const float* x    = (const float*)d_in[0];
  const float* Wq   = (const float*)d_in[1];
  const float* Wk   = (const float*)d_in[2];
  const float* Wv   = (const float*)d_in[3];
  const float* Wb   = (const float*)d_in[4];
  const float* Wtg  = (const float*)d_in[5];
  const float* ml   = (const float*)d_in[6];
  const float* ldc  = (const float*)d_in[7];
  const float* oms  = (const float*)d_in[8];
  const float* Wg   = (const float*)d_in[9];
  const float* Wo   = (const float*)d_in[10];
  float* out = (float*)d_out;

  proj_gemm_kernel<<<dim3(NPROJ / 64, NROWS / 64), 256>>>(x, Wq, Wk, Wv, Wb, Wtg, Wg);
  scan_kernel<<<BB * HH * RRm, 256>>>(ml, ldc, oms);
  reduce_y_kernel<<<(NROWS * 512 / 4 + 255) / 256, 256>>>();
  out_gemm_kernel<<<dim3(DD / 64, NROWS / 64), 256>>>(Wo, out);
}

// round 8
// speedup vs baseline: 1.8175x; 1.0062x over previous
#include <cuda_runtime.h>
#include <math.h>

// Problem constants
#define BB 2
#define TT 128
#define DD 1024
#define HH 8
#define RRm 8
#define DK 64
#define DV 64
#define NPROJ 2176           // 512 q | 512 k | 512 v | 64 beta | 64 tg | 512 g
#define NROWS 256            // B*T
#define CH 16                // scan chunk (timesteps staged in smem)

typedef unsigned long long u64;

// Scratch (no allocations allowed). Split-K partials: [2] halves each.
__device__ __align__(16) float g_proj[2 * NROWS * NPROJ];      // 4.4 MB (raw, pre-sigmoid)
__device__ __align__(16) float g_yr[RRm * NROWS * 512];        // 4 MB  (per-r mode reads)
__device__ __align__(16) float g_a[NROWS * 512];               // 512 KB (gated, r-reduced)
__device__ __align__(16) float g_o[2 * NROWS * DD];            // 2 MB  (out partials)

// ---------------------------------------------------------------------------
// f32x2 helpers (ptxas never emits FFMA2 from C++; PTX only)
// ---------------------------------------------------------------------------
__device__ __forceinline__ u64 pack2(float lo, float hi) {
  u64 r; asm("mov.b64 %0, {%1, %2};" : "=l"(r) : "f"(lo), "f"(hi)); return r;
}
__device__ __forceinline__ void unpack2(u64 v, float& lo, float& hi) {
  asm("mov.b64 {%0, %1}, %2;" : "=f"(lo), "=f"(hi) : "l"(v));
}
__device__ __forceinline__ u64 fma2(u64 a, u64 b, u64 c) {
  u64 d; asm("fma.rn.f32x2 %0, %1, %2, %3;" : "=l"(d) : "l"(a), "l"(b), "l"(c)); return d;
}
__device__ __forceinline__ u64 mul2(u64 a, u64 b) {
  u64 d; asm("mul.rn.f32x2 %0, %1, %2;" : "=l"(d) : "l"(a), "l"(b)); return d;
}
__device__ __forceinline__ u64 neg2(u64 a) { return a ^ 0x8000000080000000ULL; }

union F4U { float4 f; u64 u[2]; };

__device__ __forceinline__ float sigmoidf_(float x) { return 1.f / (1.f + expf(-x)); }

// ---------------------------------------------------------------------------
// Fused projection GEMM, split-K=2: g_proj[z] = x[:, z*512:(z+1)*512] @ W-half
// grid (34, 4, 2) = 272 CTAs, 256 threads, 4x4 microtile, double-buffered.
// Pure GEMM: sigmoid moved into consumers (scan / reduce_y).
// ---------------------------------------------------------------------------
__global__ __launch_bounds__(256) void proj_gemm_kernel(
    const float* __restrict__ x,
    const float* __restrict__ Wq, const float* __restrict__ Wk,
    const float* __restrict__ Wv, const float* __restrict__ Wb,
    const float* __restrict__ Wtg, const float* __restrict__ Wg) {
  __shared__ float As[2][16][68];
  __shared__ float Bs[2][16][64];

  const int colBase = blockIdx.x * 64;
  const int rowBase = blockIdx.y * 64;
  const int kOff = blockIdx.z * 512;

  const float* W; int lc, ldw;
  if (colBase < 512)       { W = Wq;  lc = colBase;        ldw = 512; }
  else if (colBase < 1024) { W = Wk;  lc = colBase - 512;  ldw = 512; }
  else if (colBase < 1536) { W = Wv;  lc = colBase - 1024; ldw = 512; }
  else if (colBase < 1600) { W = Wb;  lc = colBase - 1536; ldw = 64;  }
  else if (colBase < 1664) { W = Wtg; lc = colBase - 1600; ldw = 64;  }
  else                     { W = Wg;  lc = colBase - 1664; ldw = 512; }

  const int tid = threadIdx.x;
  const int ty = tid >> 4, tx = tid & 15;           // compute: rows ty*4+, cols tx*4+
  const int lrA = tid >> 2, kgA = (tid & 3) * 4;    // A: row lrA, k kgA..+3
  const int lkB = tid >> 4, c4B = (tid & 15) << 2;  // B: k lkB, cols c4B..+3

  u64 acc[4][2];
#pragma unroll
  for (int i = 0; i < 4; i++) { acc[i][0] = 0ULL; acc[i][1] = 0ULL; }

  const int NIT = 512 / 16;
  float4 av, bv;
  av = *(const float4*)(x + (rowBase + lrA) * DD + kOff + kgA);
  bv = *(const float4*)(W + (kOff + lkB) * ldw + lc + c4B);
  As[0][kgA + 0][lrA] = av.x; As[0][kgA + 1][lrA] = av.y;
  As[0][kgA + 2][lrA] = av.z; As[0][kgA + 3][lrA] = av.w;
  *(float4*)(&Bs[0][lkB][c4B]) = bv;
  __syncthreads();

  int cur = 0;
  for (int i = 0; i < NIT; i++) {
    if (i + 1 < NIT) {
      int kb = kOff + (i + 1) * 16;
      av = *(const float4*)(x + (rowBase + lrA) * DD + kb + kgA);
      bv = *(const float4*)(W + (kb + lkB) * ldw + lc + c4B);
    }
#pragma unroll
    for (int kk = 0; kk < 16; kk++) {
      float4 a = *(float4*)(&As[cur][kk][ty * 4]);
      F4U bb; bb.f = *(float4*)(&Bs[cur][kk][tx * 4]);
      u64 a0 = pack2(a.x, a.x);
      u64 a1 = pack2(a.y, a.y);
      u64 a2 = pack2(a.z, a.z);
      u64 a3 = pack2(a.w, a.w);
      acc[0][0] = fma2(a0, bb.u[0], acc[0][0]);
      acc[0][1] = fma2(a0, bb.u[1], acc[0][1]);
      acc[1][0] = fma2(a1, bb.u[0], acc[1][0]);
      acc[1][1] = fma2(a1, bb.u[1], acc[1][1]);
      acc[2][0] = fma2(a2, bb.u[0], acc[2][0]);
      acc[2][1] = fma2(a2, bb.u[1], acc[2][1]);
      acc[3][0] = fma2(a3, bb.u[0], acc[3][0]);
      acc[3][1] = fma2(a3, bb.u[1], acc[3][1]);
    }
    if (i + 1 < NIT) {
      int nxt = cur ^ 1;
      As[nxt][kgA + 0][lrA] = av.x; As[nxt][kgA + 1][lrA] = av.y;
      As[nxt][kgA + 2][lrA] = av.z; As[nxt][kgA + 3][lrA] = av.w;
      *(float4*)(&Bs[nxt][lkB][c4B]) = bv;
      __syncthreads();
      cur = nxt;
    }
  }

  float* outp = g_proj + blockIdx.z * (NROWS * NPROJ);
#pragma unroll
  for (int j = 0; j < 4; j++) {
    F4U o; o.u[0] = acc[j][0]; o.u[1] = acc[j][1];
    *(float4*)(outp + (rowBase + ty * 4 + j) * NPROJ + colBase + tx * 4) = o.f;
  }
}

// ---------------------------------------------------------------------------
// Sequential scan. One CTA per (b,h,r) chain: 128 CTAs, 256 threads.
// q/k/v/beta/tg for CH=16 steps staged in smem (summing the two split-K
// proj halves; sigmoid applied to beta/tg here). Double-buffered, one sync
// per chunk. Thread owns v = tid/4, k-slice [16*(tid%4), +16) as 8 f32x2.
// ---------------------------------------------------------------------------
__global__ __launch_bounds__(256) void scan_kernel(
    const float* __restrict__ mode_logits,
    const float* __restrict__ log_decay,
    const float* __restrict__ omega_log_scale) {
  __shared__ float sQ[2][CH][64];
  __shared__ float sK[2][CH][64];
  __shared__ float sV[2][CH][64];
  __shared__ float sB[2][CH];
  __shared__ float sT[2][CH];

  const int cid = blockIdx.x;        // 0..127
  const int b = cid >> 6;
  const int h = (cid >> 3) & 7;
  const int r = cid & 7;
  const int tid = threadIdx.x;
  const int v = tid >> 2;
  const int q4 = tid & 3;
  const int k0 = q4 * 16;

  // mode weight: softmax over R for this head
  float ml[RRm];
  float mx = -1e30f;
#pragma unroll
  for (int i = 0; i < RRm; i++) { ml[i] = mode_logits[h * RRm + i]; mx = fmaxf(mx, ml[i]); }
  float ssum = 0.f;
#pragma unroll
  for (int i = 0; i < RRm; i++) ssum += expf(ml[i] - mx);
  const float mw = expf(ml[r] - mx) / ssum;

  // rho = exp(-softplus(log_decay))
  const float ldv = log_decay[h * RRm + r];
  const float sp = (ldv > 20.f) ? ldv : log1pf(expf(ldv));
  const float rho = expf(-sp);
  const float osc = expf(omega_log_scale[h * RRm + r]);

  u64 cw2[8], sw2[8], sr2[8], si2[8];
  const float c_ln = 9.210340371976184f / 64.f;  // ln(10000)/64
#pragma unroll
  for (int p = 0; p < 8; p++) {
    float pv = (float)(k0 + 2 * p);              // even -> (k & ~1) identical for pair
    float om = osc * expf(-pv * c_ln);
    float c = cosf(om), s = sinf(om);
    cw2[p] = pack2(c, c);
    sw2[p] = pack2(s, s);
    sr2[p] = 0ULL;
    si2[p] = 0ULL;
  }

  // Cooperative chunk loading: thread -> (step ls, float4 part lp)
  const int ls = tid >> 4;       // 0..15
  const int lp = tid & 15;       // 0..15
  const float* gp0 = g_proj + (b * TT) * NPROJ;
  const float* gp1 = g_proj + NROWS * NPROJ + (b * TT) * NPROJ;
  float* ybase = g_yr + r * (NROWS * 512) + (b * TT) * 512 + h * DV + v;

  float4 qf, kf, vf;
  float bf = 0.f, tf = 0.f;
  {
    const int ro = ls * NPROJ + h * 64;
    float4 t0, t1;
    t0 = *(const float4*)(gp0 + ro + lp * 4);       t1 = *(const float4*)(gp1 + ro + lp * 4);
    qf.x = t0.x + t1.x; qf.y = t0.y + t1.y; qf.z = t0.z + t1.z; qf.w = t0.w + t1.w;
    t0 = *(const float4*)(gp0 + ro + 512 + lp * 4); t1 = *(const float4*)(gp1 + ro + 512 + lp * 4);
    kf.x = t0.x + t1.x; kf.y = t0.y + t1.y; kf.z = t0.z + t1.z; kf.w = t0.w + t1.w;
    t0 = *(const float4*)(gp0 + ro + 1024 + lp * 4); t1 = *(const float4*)(gp1 + ro + 1024 + lp * 4);
    vf.x = t0.x + t1.x; vf.y = t0.y + t1.y; vf.z = t0.z + t1.z; vf.w = t0.w + t1.w;
    if (lp == 0) {
      int bo = ls * NPROJ + 1536 + h * RRm + r;
      bf = sigmoidf_(gp0[bo] + gp1[bo]);
    }
    if (lp == 1) {
      int to = ls * NPROJ + 1600 + h * RRm + r;
      tf = sigmoidf_(gp0[to] + gp1[to]);
    }
  }
  *(float4*)(&sQ[0][ls][lp * 4]) = qf;
  *(float4*)(&sK[0][ls][lp * 4]) = kf;
  *(float4*)(&sV[0][ls][lp * 4]) = vf;
  if (lp == 0) sB[0][ls] = bf;
  if (lp == 1) sT[0][ls] = tf;
  __syncthreads();

  const int NCH = TT / CH;
  int cur = 0;
  for (int c = 0; c < NCH; c++) {
    // Prefetch next chunk into registers (overlaps with the 16-step compute)
    if (c + 1 < NCH) {
      const int ro = ((c + 1) * CH + ls) * NPROJ + h * 64;
      float4 t0, t1;
      t0 = *(const float4*)(gp0 + ro + lp * 4);       t1 = *(const float4*)(gp1 + ro + lp * 4);
      qf.x = t0.x + t1.x; qf.y = t0.y + t1.y; qf.z = t0.z + t1.z; qf.w = t0.w + t1.w;
      t0 = *(const float4*)(gp0 + ro + 512 + lp * 4); t1 = *(const float4*)(gp1 + ro + 512 + lp * 4);
      kf.x = t0.x + t1.x; kf.y = t0.y + t1.y; kf.z = t0.z + t1.z; kf.w = t0.w + t1.w;
      t0 = *(const float4*)(gp0 + ro + 1024 + lp * 4); t1 = *(const float4*)(gp1 + ro + 1024 + lp * 4);
      vf.x = t0.x + t1.x; vf.y = t0.y + t1.y; vf.z = t0.z + t1.z; vf.w = t0.w + t1.w;
      if (lp == 0) {
        int bo = ((c + 1) * CH + ls) * NPROJ + 1536 + h * RRm + r;
        bf = sigmoidf_(gp0[bo] + gp1[bo]);
      }
      if (lp == 1) {
        int to = ((c + 1) * CH + ls) * NPROJ + 1600 + h * RRm + r;
        tf = sigmoidf_(gp0[to] + gp1[to]);
      }
    }

    for (int tt = 0; tt < CH; tt++) {
      u64 kt2[8], qt2[8];
#pragma unroll
      for (int g4 = 0; g4 < 4; g4++) {
        F4U kv; kv.f = *(const float4*)(&sK[cur][tt][k0 + g4 * 4]);
        F4U qv; qv.f = *(const float4*)(&sQ[cur][tt][k0 + g4 * 4]);
        kt2[g4 * 2 + 0] = kv.u[0]; kt2[g4 * 2 + 1] = kv.u[1];
        qt2[g4 * 2 + 0] = qv.u[0]; qt2[g4 * 2 + 1] = qv.u[1];
      }
      const float vtv  = sV[cur][tt][v];
      const float beta = sB[cur][tt];
      const float tg   = sT[cur][tt];
      const float decay = tg * rho;
      const u64 decay2 = pack2(decay, decay);

      // rotate state (complex mult by decay * e^{i omega}) + pred partial
      u64 predA = 0ULL, predB = 0ULL;
#pragma unroll
      for (int p = 0; p < 8; p++) {
        u64 dc = mul2(decay2, cw2[p]);
        u64 ds = mul2(decay2, sw2[p]);
        u64 m1 = mul2(ds, si2[p]);
        u64 rr = fma2(dc, sr2[p], neg2(m1));
        u64 m2 = mul2(dc, si2[p]);
        si2[p] = fma2(ds, sr2[p], m2);
        sr2[p] = rr;                       // sr temporarily holds rot_r
        if (p & 1) predB = fma2(rr, kt2[p], predB);
        else       predA = fma2(rr, kt2[p], predA);
      }
      float alo, ahi, blo, bhi;
      unpack2(predA, alo, ahi); unpack2(predB, blo, bhi);
      float pred = (alo + blo) + (ahi + bhi);
      pred += __shfl_xor_sync(0xffffffffu, pred, 1);
      pred += __shfl_xor_sync(0xffffffffu, pred, 2);

      const float w = beta * (vtv - pred);
      const u64 w2 = pack2(w, w);

      u64 rdA = 0ULL, rdB = 0ULL;
#pragma unroll
      for (int p = 0; p < 8; p++) {
        sr2[p] = fma2(w2, kt2[p], sr2[p]); // sr_new = rot_r + beta*err*k
        if (p & 1) rdB = fma2(sr2[p], qt2[p], rdB);
        else       rdA = fma2(sr2[p], qt2[p], rdA);
      }
      float r0lo, r0hi, r1lo, r1hi;
      unpack2(rdA, r0lo, r0hi); unpack2(rdB, r1lo, r1hi);
      float rd = (r0lo + r1lo) + (r0hi + r1hi);
      rd += __shfl_xor_sync(0xffffffffu, rd, 1);
      rd += __shfl_xor_sync(0xffffffffu, rd, 2);

      if (q4 == 0) ybase[(c * CH + tt) * 512] = mw * rd;
    }

    if (c + 1 < NCH) {
      int nxt = cur ^ 1;
      *(float4*)(&sQ[nxt][ls][lp * 4]) = qf;
      *(float4*)(&sK[nxt][ls][lp * 4]) = kf;
      *(float4*)(&sV[nxt][ls][lp * 4]) = vf;
      if (lp == 0) sB[nxt][ls] = bf;
      if (lp == 1) sT[nxt][ls] = tf;
      __syncthreads();
      cur = nxt;
    }
  }
}

// ---------------------------------------------------------------------------
// Reduce over r + apply gate: g_a[row][c] = sigmoid(g0+g1) * sum_r g_yr
// ---------------------------------------------------------------------------
__global__ __launch_bounds__(256) void reduce_y_kernel() {
  int idx = blockIdx.x * blockDim.x + threadIdx.x;   // float4 index
  if (idx >= NROWS * 512 / 4) return;
  int row = idx >> 7;           // 128 float4 per row
  int c4 = (idx & 127) << 2;
  float4 s = *(const float4*)(g_yr + row * 512 + c4);
#pragma unroll
  for (int r = 1; r < RRm; r++) {
    float4 t = *(const float4*)(g_yr + r * (NROWS * 512) + row * 512 + c4);
    s.x += t.x; s.y += t.y; s.z += t.z; s.w += t.w;
  }
  float4 g0 = *(const float4*)(g_proj + row * NPROJ + 1664 + c4);
  float4 g1 = *(const float4*)(g_proj + NROWS * NPROJ + row * NPROJ + 1664 + c4);
  s.x *= sigmoidf_(g0.x + g1.x);
  s.y *= sigmoidf_(g0.y + g1.y);
  s.z *= sigmoidf_(g0.z + g1.z);
  s.w *= sigmoidf_(g0.w + g1.w);
  *(float4*)(g_a + row * 512 + c4) = s;
}

// ---------------------------------------------------------------------------
// Output GEMM, split-K=2: g_o[z] = g_a[:, z*256:+256] @ Wo-half
// grid (16, 4, 2) = 128 CTAs, 256 threads, 4x4 microtile, double-buffered.
// ---------------------------------------------------------------------------
__global__ __launch_bounds__(256) void out_gemm_kernel(
    const float* __restrict__ Wo) {
  __shared__ float As[2][16][68];
  __shared__ float Bs[2][16][64];

  const int colBase = blockIdx.x * 64;  // 0..1023
  const int rowBase = blockIdx.y * 64;  // 0..255
  const int kOff = blockIdx.z * 256;

  const int tid = threadIdx.x;
  const int ty = tid >> 4, tx = tid & 15;
  const int lrA = tid >> 2, kgA = (tid & 3) * 4;
  const int lkB = tid >> 4, c4B = (tid & 15) << 2;

  u64 acc[4][2];
#pragma unroll
  for (int i = 0; i < 4; i++) { acc[i][0] = 0ULL; acc[i][1] = 0ULL; }

  const int NIT = 256 / 16;
  float4 av, bv;
  av = *(const float4*)(g_a + (rowBase + lrA) * 512 + kOff + kgA);
  bv = *(const float4*)(Wo + (kOff + lkB) * DD + colBase + c4B);
  As[0][kgA + 0][lrA] = av.x; As[0][kgA + 1][lrA] = av.y;
  As[0][kgA + 2][lrA] = av.z; As[0][kgA + 3][lrA] = av.w;
  *(float4*)(&Bs[0][lkB][c4B]) = bv;
  __syncthreads();

  int cur = 0;
  for (int i = 0; i < NIT; i++) {
    if (i + 1 < NIT) {
      int kb = kOff + (i + 1) * 16;
      av = *(const float4*)(g_a + (rowBase + lrA) * 512 + kb + kgA);
      bv = *(const float4*)(Wo + (kb + lkB) * DD + colBase + c4B);
    }
#pragma unroll
    for (int kk = 0; kk < 16; kk++) {
      float4 a = *(float4*)(&As[cur][kk][ty * 4]);
      F4U bb; bb.f = *(float4*)(&Bs[cur][kk][tx * 4]);
      u64 a0 = pack2(a.x, a.x);
      u64 a1 = pack2(a.y, a.y);
      u64 a2 = pack2(a.z, a.z);
      u64 a3 = pack2(a.w, a.w);
      acc[0][0] = fma2(a0, bb.u[0], acc[0][0]);
      acc[0][1] = fma2(a0, bb.u[1], acc[0][1]);
      acc[1][0] = fma2(a1, bb.u[0], acc[1][0]);
      acc[1][1] = fma2(a1, bb.u[1], acc[1][1]);
      acc[2][0] = fma2(a2, bb.u[0], acc[2][0]);
      acc[2][1] = fma2(a2, bb.u[1], acc[2][1]);
      acc[3][0] = fma2(a3, bb.u[0], acc[3][0]);
      acc[3][1] = fma2(a3, bb.u[1], acc[3][1]);
    }
    if (i + 1 < NIT) {
      int nxt = cur ^ 1;
      As[nxt][kgA + 0][lrA] = av.x; As[nxt][kgA + 1][lrA] = av.y;
      As[nxt][kgA + 2][lrA] = av.z; As[nxt][kgA + 3][lrA] = av.w;
      *(float4*)(&Bs[nxt][lkB][c4B]) = bv;
      __syncthreads();
      cur = nxt;
    }
  }

  float* outp = g_o + blockIdx.z * (NROWS * DD);
#pragma unroll
  for (int j = 0; j < 4; j++) {
    F4U o; o.u[0] = acc[j][0]; o.u[1] = acc[j][1];
    *(float4*)(outp + (rowBase + ty * 4 + j) * DD + colBase + tx * 4) = o.f;
  }
}

// ---------------------------------------------------------------------------
// Sum the two out partials into d_out.
// ---------------------------------------------------------------------------
__global__ __launch_bounds__(256) void out_sum_kernel(float* __restrict__ out) {
  int idx = blockIdx.x * blockDim.x + threadIdx.x;   // float4 index
  if (idx >= NROWS * DD / 4) return;
  float4 a = *(const float4*)(g_o + idx * 4);
  float4 b = *(const float4*)(g_o + NROWS * DD + idx * 4);
  float4 s; s.x = a.x + b.x; s.y = a.y + b.y; s.z = a.z + b.z; s.w = a.w + b.w;
  *(float4*)(out + idx * 4) = s;
}

// ---------------------------------------------------------------------------
// Entry point
// ---------------------------------------------------------------------------
extern "C" void kernel_launch(void* const* d_in, const int* in_sizes, int n_in,
                              void* d_out, int out_size) {
  const float* x    = (const float*)d_in[0];
  const float* Wq   = (const float*)d_in[1];
  const float* Wk   = (const float*)d_in[2];
  const float* Wv   = (const float*)d_in[3];
  const float* Wb   = (const float*)d_in[4];
  const float* Wtg  = (const float*)d_in[5];
  const float* ml   = (const float*)d_in[6];
  const float* ldc  = (const float*)d_in[7];
  const float* oms  = (const float*)d_in[8];
  const float* Wg   = (const float*)d_in[9];
  const float* Wo   = (const float*)d_in[10];
  float* out = (float*)d_out;

  proj_gemm_kernel<<<dim3(NPROJ / 64, NROWS / 64, 2), 256>>>(x, Wq, Wk, Wv, Wb, Wtg, Wg);
  scan_kernel<<<BB * HH * RRm, 256>>>(ml, ldc, oms);
  reduce_y_kernel<<<(NROWS * 512 / 4 + 255) / 256, 256>>>();
  out_gemm_kernel<<<dim3(DD / 64, NROWS / 64, 2), 256>>>(Wo);
  out_sum_kernel<<<(NROWS * DD / 4 + 255) / 256, 256>>>(out);
}

// round 11
// speedup vs baseline: 1.9100x; 1.0509x over previous
#include <cuda_runtime.h>
#include <math.h>

// Problem constants
#define BB 2
#define TT 128
#define DD 1024
#define HH 8
#define RRm 8
#define DK 64
#define DV 64
#define NPROJ 2176           // 512 q | 512 k | 512 v | 64 beta | 64 tg | 512 g
#define NROWS 256            // B*T
#define CH 16                // scan chunk (timesteps staged in smem)

typedef unsigned long long u64;

// Scratch (no allocations allowed)
__device__ __align__(16) float g_proj[2 * NROWS * NPROJ];      // split-K partials (raw)
__device__ __align__(16) float g_projc[NROWS * NPROJ];         // combined + activated
__device__ __align__(16) float g_yr[RRm * NROWS * 512];        // per-r mode reads
__device__ __align__(16) float g_a[NROWS * 512];               // gated, r-reduced
__device__ __align__(16) float g_o[2 * NROWS * DD];            // out partials

// ---------------------------------------------------------------------------
// f32x2 helpers (ptxas never emits FFMA2 from C++; PTX only)
// ---------------------------------------------------------------------------
__device__ __forceinline__ u64 pack2(float lo, float hi) {
  u64 r; asm("mov.b64 %0, {%1, %2};" : "=l"(r) : "f"(lo), "f"(hi)); return r;
}
__device__ __forceinline__ void unpack2(u64 v, float& lo, float& hi) {
  asm("mov.b64 {%0, %1}, %2;" : "=f"(lo), "=f"(hi) : "l"(v));
}
__device__ __forceinline__ u64 fma2(u64 a, u64 b, u64 c) {
  u64 d; asm("fma.rn.f32x2 %0, %1, %2, %3;" : "=l"(d) : "l"(a), "l"(b), "l"(c)); return d;
}
__device__ __forceinline__ u64 mul2(u64 a, u64 b) {
  u64 d; asm("mul.rn.f32x2 %0, %1, %2;" : "=l"(d) : "l"(a), "l"(b)); return d;
}
__device__ __forceinline__ u64 neg2(u64 a) { return a ^ 0x8000000080000000ULL; }

union F4U { float4 f; u64 u[2]; };

__device__ __forceinline__ float sigmoidf_(float x) { return 1.f / (1.f + expf(-x)); }

// ---------------------------------------------------------------------------
// Fused projection GEMM, split-K=2: g_proj[z] = x[:, z*512:+512] @ W-half
// grid (34, 4, 2) = 272 CTAs, 256 threads, 4x4 microtile, double-buffered.
// ---------------------------------------------------------------------------
__global__ __launch_bounds__(256) void proj_gemm_kernel(
    const float* __restrict__ x,
    const float* __restrict__ Wq, const float* __restrict__ Wk,
    const float* __restrict__ Wv, const float* __restrict__ Wb,
    const float* __restrict__ Wtg, const float* __restrict__ Wg) {
  __shared__ float As[2][16][68];
  __shared__ float Bs[2][16][64];

  const int colBase = blockIdx.x * 64;
  const int rowBase = blockIdx.y * 64;
  const int kOff = blockIdx.z * 512;

  const float* W; int lc, ldw;
  if (colBase < 512)       { W = Wq;  lc = colBase;        ldw = 512; }
  else if (colBase < 1024) { W = Wk;  lc = colBase - 512;  ldw = 512; }
  else if (colBase < 1536) { W = Wv;  lc = colBase - 1024; ldw = 512; }
  else if (colBase < 1600) { W = Wb;  lc = colBase - 1536; ldw = 64;  }
  else if (colBase < 1664) { W = Wtg; lc = colBase - 1600; ldw = 64;  }
  else                     { W = Wg;  lc = colBase - 1664; ldw = 512; }

  const int tid = threadIdx.x;
  const int ty = tid >> 4, tx = tid & 15;
  const int lrA = tid >> 2, kgA = (tid & 3) * 4;
  const int lkB = tid >> 4, c4B = (tid & 15) << 2;

  u64 acc[4][2];
#pragma unroll
  for (int i = 0; i < 4; i++) { acc[i][0] = 0ULL; acc[i][1] = 0ULL; }

  const int NIT = 512 / 16;
  float4 av, bv;
  av = *(const float4*)(x + (rowBase + lrA) * DD + kOff + kgA);
  bv = *(const float4*)(W + (kOff + lkB) * ldw + lc + c4B);
  As[0][kgA + 0][lrA] = av.x; As[0][kgA + 1][lrA] = av.y;
  As[0][kgA + 2][lrA] = av.z; As[0][kgA + 3][lrA] = av.w;
  *(float4*)(&Bs[0][lkB][c4B]) = bv;
  __syncthreads();

  int cur = 0;
  for (int i = 0; i < NIT; i++) {
    if (i + 1 < NIT) {
      int kb = kOff + (i + 1) * 16;
      av = *(const float4*)(x + (rowBase + lrA) * DD + kb + kgA);
      bv = *(const float4*)(W + (kb + lkB) * ldw + lc + c4B);
    }
#pragma unroll
    for (int kk = 0; kk < 16; kk++) {
      float4 a = *(float4*)(&As[cur][kk][ty * 4]);
      F4U bb; bb.f = *(float4*)(&Bs[cur][kk][tx * 4]);
      u64 a0 = pack2(a.x, a.x);
      u64 a1 = pack2(a.y, a.y);
      u64 a2 = pack2(a.z, a.z);
      u64 a3 = pack2(a.w, a.w);
      acc[0][0] = fma2(a0, bb.u[0], acc[0][0]);
      acc[0][1] = fma2(a0, bb.u[1], acc[0][1]);
      acc[1][0] = fma2(a1, bb.u[0], acc[1][0]);
      acc[1][1] = fma2(a1, bb.u[1], acc[1][1]);
      acc[2][0] = fma2(a2, bb.u[0], acc[2][0]);
      acc[2][1] = fma2(a2, bb.u[1], acc[2][1]);
      acc[3][0] = fma2(a3, bb.u[0], acc[3][0]);
      acc[3][1] = fma2(a3, bb.u[1], acc[3][1]);
    }
    if (i + 1 < NIT) {
      int nxt = cur ^ 1;
      As[nxt][kgA + 0][lrA] = av.x; As[nxt][kgA + 1][lrA] = av.y;
      As[nxt][kgA + 2][lrA] = av.z; As[nxt][kgA + 3][lrA] = av.w;
      *(float4*)(&Bs[nxt][lkB][c4B]) = bv;
      __syncthreads();
      cur = nxt;
    }
  }

  float* outp = g_proj + blockIdx.z * (NROWS * NPROJ);
#pragma unroll
  for (int j = 0; j < 4; j++) {
    F4U o; o.u[0] = acc[j][0]; o.u[1] = acc[j][1];
    *(float4*)(outp + (rowBase + ty * 4 + j) * NPROJ + colBase + tx * 4) = o.f;
  }
}

// ---------------------------------------------------------------------------
// Combine split-K proj halves + apply sigmoid to activation cols (>=1536).
// ---------------------------------------------------------------------------
__global__ __launch_bounds__(256) void proj_combine_kernel() {
  int idx = blockIdx.x * blockDim.x + threadIdx.x;   // float4 index
  if (idx >= NROWS * NPROJ / 4) return;
  int e = idx * 4;
  int col = e % NPROJ;
  float4 a = *(const float4*)(g_proj + e);
  float4 b = *(const float4*)(g_proj + NROWS * NPROJ + e);
  float4 s; s.x = a.x + b.x; s.y = a.y + b.y; s.z = a.z + b.z; s.w = a.w + b.w;
  if (col >= 1536) {
    s.x = sigmoidf_(s.x); s.y = sigmoidf_(s.y);
    s.z = sigmoidf_(s.z); s.w = sigmoidf_(s.w);
  }
  *(float4*)(g_projc + e) = s;
}

// ---------------------------------------------------------------------------
// Sequential scan. One CTA per (b,h,r) chain: 128 CTAs, 256 threads.
// CH=16 steps staged in smem from the combined buffer (single read).
// Critical-path trick: rd = rotq + w*kq where rotq = sum(rot_r*q) and
// kq = sum(k*q) accumulate in the SAME loop as pred -> only one dependent
// shfl round on the serial chain; the three reductions' latencies overlap.
// ---------------------------------------------------------------------------
__global__ __launch_bounds__(256) void scan_kernel(
    const float* __restrict__ mode_logits,
    const float* __restrict__ log_decay,
    const float* __restrict__ omega_log_scale) {
  __shared__ float sQ[2][CH][64];
  __shared__ float sK[2][CH][64];
  __shared__ float sV[2][CH][64];
  __shared__ float sB[2][CH];
  __shared__ float sT[2][CH];

  const int cid = blockIdx.x;        // 0..127
  const int b = cid >> 6;
  const int h = (cid >> 3) & 7;
  const int r = cid & 7;
  const int tid = threadIdx.x;
  const int v = tid >> 2;
  const int q4 = tid & 3;
  const int k0 = q4 * 16;

  // mode weight: softmax over R for this head
  float ml[RRm];
  float mx = -1e30f;
#pragma unroll
  for (int i = 0; i < RRm; i++) { ml[i] = mode_logits[h * RRm + i]; mx = fmaxf(mx, ml[i]); }
  float ssum = 0.f;
#pragma unroll
  for (int i = 0; i < RRm; i++) ssum += expf(ml[i] - mx);
  const float mw = expf(ml[r] - mx) / ssum;

  // rho = exp(-softplus(log_decay))
  const float ldv = log_decay[h * RRm + r];
  const float sp = (ldv > 20.f) ? ldv : log1pf(expf(ldv));
  const float rho = expf(-sp);
  const float osc = expf(omega_log_scale[h * RRm + r]);

  u64 cw2[8], sw2[8], sr2[8], si2[8];
  const float c_ln = 9.210340371976184f / 64.f;  // ln(10000)/64
#pragma unroll
  for (int p = 0; p < 8; p++) {
    float pv = (float)(k0 + 2 * p);              // even -> (k & ~1) identical for pair
    float om = osc * expf(-pv * c_ln);
    float c = cosf(om), s = sinf(om);
    cw2[p] = pack2(c, c);
    sw2[p] = pack2(s, s);
    sr2[p] = 0ULL;
    si2[p] = 0ULL;
  }

  // Cooperative chunk loading: thread -> (step ls, float4 part lp)
  const int ls = tid >> 4;       // 0..15
  const int lp = tid & 15;       // 0..15
  const float* gpb = g_projc + (b * TT) * NPROJ;
  float* ybase = g_yr + r * (NROWS * 512) + (b * TT) * 512 + h * DV + v;

  float4 qf, kf, vf;
  float bf = 0.f, tf = 0.f;
  {
    const float* row = gpb + ls * NPROJ + h * 64;
    qf = *(const float4*)(row + lp * 4);
    kf = *(const float4*)(row + 512 + lp * 4);
    vf = *(const float4*)(row + 1024 + lp * 4);
    if (lp == 0) bf = gpb[ls * NPROJ + 1536 + h * RRm + r];
    if (lp == 1) tf = gpb[ls * NPROJ + 1600 + h * RRm + r];
  }
  *(float4*)(&sQ[0][ls][lp * 4]) = qf;
  *(float4*)(&sK[0][ls][lp * 4]) = kf;
  *(float4*)(&sV[0][ls][lp * 4]) = vf;
  if (lp == 0) sB[0][ls] = bf;
  if (lp == 1) sT[0][ls] = tf;
  __syncthreads();

  const int NCH = TT / CH;
  int cur = 0;
  for (int c = 0; c < NCH; c++) {
    // Prefetch next chunk into registers (overlaps with the 16-step compute)
    if (c + 1 < NCH) {
      const float* row = gpb + ((c + 1) * CH + ls) * NPROJ + h * 64;
      qf = *(const float4*)(row + lp * 4);
      kf = *(const float4*)(row + 512 + lp * 4);
      vf = *(const float4*)(row + 1024 + lp * 4);
      if (lp == 0) bf = gpb[((c + 1) * CH + ls) * NPROJ + 1536 + h * RRm + r];
      if (lp == 1) tf = gpb[((c + 1) * CH + ls) * NPROJ + 1600 + h * RRm + r];
    }

    for (int tt = 0; tt < CH; tt++) {
      u64 kt2[8], qt2[8];
#pragma unroll
      for (int g4 = 0; g4 < 4; g4++) {
        F4U kv; kv.f = *(const float4*)(&sK[cur][tt][k0 + g4 * 4]);
        F4U qv; qv.f = *(const float4*)(&sQ[cur][tt][k0 + g4 * 4]);
        kt2[g4 * 2 + 0] = kv.u[0]; kt2[g4 * 2 + 1] = kv.u[1];
        qt2[g4 * 2 + 0] = qv.u[0]; qt2[g4 * 2 + 1] = qv.u[1];
      }
      const float vtv  = sV[cur][tt][v];
      const float beta = sB[cur][tt];
      const float tg   = sT[cur][tt];
      const float decay = tg * rho;
      const u64 decay2 = pack2(decay, decay);

      // rotation + three accumulators (pred critical; rotq/kq off-path)
      u64 predA = 0ULL, predB = 0ULL, rotq2 = 0ULL, kq2 = 0ULL;
#pragma unroll
      for (int p = 0; p < 8; p++) {
        u64 dc = mul2(decay2, cw2[p]);
        u64 ds = mul2(decay2, sw2[p]);
        u64 m1 = mul2(ds, si2[p]);
        u64 rr = fma2(dc, sr2[p], neg2(m1));
        u64 m2 = mul2(dc, si2[p]);
        si2[p] = fma2(ds, sr2[p], m2);
        sr2[p] = rr;                       // sr temporarily holds rot_r
        if (p & 1) predB = fma2(rr, kt2[p], predB);
        else       predA = fma2(rr, kt2[p], predA);
        rotq2 = fma2(rr, qt2[p], rotq2);
        kq2   = fma2(kt2[p], qt2[p], kq2);
      }
      float alo, ahi, blo, bhi;
      unpack2(predA, alo, ahi); unpack2(predB, blo, bhi);
      float pred = (alo + blo) + (ahi + bhi);
      float rqlo, rqhi, kqlo, kqhi;
      unpack2(rotq2, rqlo, rqhi); unpack2(kq2, kqlo, kqhi);
      float rotq = rqlo + rqhi;
      float kq = kqlo + kqhi;
      // three independent shfl reductions; latencies overlap
      pred += __shfl_xor_sync(0xffffffffu, pred, 1);
      rotq += __shfl_xor_sync(0xffffffffu, rotq, 1);
      kq   += __shfl_xor_sync(0xffffffffu, kq, 1);
      pred += __shfl_xor_sync(0xffffffffu, pred, 2);
      rotq += __shfl_xor_sync(0xffffffffu, rotq, 2);
      kq   += __shfl_xor_sync(0xffffffffu, kq, 2);

      const float w = beta * (vtv - pred);
      const u64 w2 = pack2(w, w);

      // state update (inter-step path); rd needs no second reduction
#pragma unroll
      for (int p = 0; p < 8; p++)
        sr2[p] = fma2(w2, kt2[p], sr2[p]); // sr_new = rot_r + beta*err*k

      if (q4 == 0) ybase[(c * CH + tt) * 512] = mw * fmaf(w, kq, rotq);
    }

    if (c + 1 < NCH) {
      int nxt = cur ^ 1;
      *(float4*)(&sQ[nxt][ls][lp * 4]) = qf;
      *(float4*)(&sK[nxt][ls][lp * 4]) = kf;
      *(float4*)(&sV[nxt][ls][lp * 4]) = vf;
      if (lp == 0) sB[nxt][ls] = bf;
      if (lp == 1) sT[nxt][ls] = tf;
      __syncthreads();
      cur = nxt;
    }
  }
}

// ---------------------------------------------------------------------------
// Reduce over r + apply gate: g_a[row][c] = gate[row][c] * sum_r g_yr
// (gate already sigmoided in g_projc)
// ---------------------------------------------------------------------------
__global__ __launch_bounds__(256) void reduce_y_kernel() {
  int idx = blockIdx.x * blockDim.x + threadIdx.x;   // float4 index
  if (idx >= NROWS * 512 / 4) return;
  int row = idx >> 7;           // 128 float4 per row
  int c4 = (idx & 127) << 2;
  float4 s = *(const float4*)(g_yr + row * 512 + c4);
#pragma unroll
  for (int r = 1; r < RRm; r++) {
    float4 t = *(const float4*)(g_yr + r * (NROWS * 512) + row * 512 + c4);
    s.x += t.x; s.y += t.y; s.z += t.z; s.w += t.w;
  }
  float4 g = *(const float4*)(g_projc + row * NPROJ + 1664 + c4);
  s.x *= g.x; s.y *= g.y; s.z *= g.z; s.w *= g.w;
  *(float4*)(g_a + row * 512 + c4) = s;
}

// ---------------------------------------------------------------------------
// Output GEMM, split-K=2: g_o[z] = g_a[:, z*256:+256] @ Wo-half
// grid (16, 4, 2) = 128 CTAs, 256 threads, 4x4 microtile, double-buffered.
// ---------------------------------------------------------------------------
__global__ __launch_bounds__(256) void out_gemm_kernel(
    const float* __restrict__ Wo) {
  __shared__ float As[2][16][68];
  __shared__ float Bs[2][16][64];

  const int colBase = blockIdx.x * 64;  // 0..1023
  const int rowBase = blockIdx.y * 64;  // 0..255
  const int kOff = blockIdx.z * 256;

  const int tid = threadIdx.x;
  const int ty = tid >> 4, tx = tid & 15;
  const int lrA = tid >> 2, kgA = (tid & 3) * 4;
  const int lkB = tid >> 4, c4B = (tid & 15) << 2;

  u64 acc[4][2];
#pragma unroll
  for (int i = 0; i < 4; i++) { acc[i][0] = 0ULL; acc[i][1] = 0ULL; }

  const int NIT = 256 / 16;
  float4 av, bv;
  av = *(const float4*)(g_a + (rowBase + lrA) * 512 + kOff + kgA);
  bv = *(const float4*)(Wo + (kOff + lkB) * DD + colBase + c4B);
  As[0][kgA + 0][lrA] = av.x; As[0][kgA + 1][lrA] = av.y;
  As[0][kgA + 2][lrA] = av.z; As[0][kgA + 3][lrA] = av.w;
  *(float4*)(&Bs[0][lkB][c4B]) = bv;
  __syncthreads();

  int cur = 0;
  for (int i = 0; i < NIT; i++) {
    if (i + 1 < NIT) {
      int kb = kOff + (i + 1) * 16;
      av = *(const float4*)(g_a + (rowBase + lrA) * 512 + kb + kgA);
      bv = *(const float4*)(Wo + (kb + lkB) * DD + colBase + c4B);
    }
#pragma unroll
    for (int kk = 0; kk < 16; kk++) {
      float4 a = *(float4*)(&As[cur][kk][ty * 4]);
      F4U bb; bb.f = *(float4*)(&Bs[cur][kk][tx * 4]);
      u64 a0 = pack2(a.x, a.x);
      u64 a1 = pack2(a.y, a.y);
      u64 a2 = pack2(a.z, a.z);
      u64 a3 = pack2(a.w, a.w);
      acc[0][0] = fma2(a0, bb.u[0], acc[0][0]);
      acc[0][1] = fma2(a0, bb.u[1], acc[0][1]);
      acc[1][0] = fma2(a1, bb.u[0], acc[1][0]);
      acc[1][1] = fma2(a1, bb.u[1], acc[1][1]);
      acc[2][0] = fma2(a2, bb.u[0], acc[2][0]);
      acc[2][1] = fma2(a2, bb.u[1], acc[2][1]);
      acc[3][0] = fma2(a3, bb.u[0], acc[3][0]);
      acc[3][1] = fma2(a3, bb.u[1], acc[3][1]);
    }
    if (i + 1 < NIT) {
      int nxt = cur ^ 1;
      As[nxt][kgA + 0][lrA] = av.x; As[nxt][kgA + 1][lrA] = av.y;
      As[nxt][kgA + 2][lrA] = av.z; As[nxt][kgA + 3][lrA] = av.w;
      *(float4*)(&Bs[nxt][lkB][c4B]) = bv;
      __syncthreads();
      cur = nxt;
    }
  }

  float* outp = g_o + blockIdx.z * (NROWS * DD);
#pragma unroll
  for (int j = 0; j < 4; j++) {
    F4U o; o.u[0] = acc[j][0]; o.u[1] = acc[j][1];
    *(float4*)(outp + (rowBase + ty * 4 + j) * DD + colBase + tx * 4) = o.f;
  }
}

// ---------------------------------------------------------------------------
// Sum the two out partials into d_out.
// ---------------------------------------------------------------------------
__global__ __launch_bounds__(256) void out_sum_kernel(float* __restrict__ out) {
  int idx = blockIdx.x * blockDim.x + threadIdx.x;   // float4 index
  if (idx >= NROWS * DD / 4) return;
  float4 a = *(const float4*)(g_o + idx * 4);
  float4 b = *(const float4*)(g_o + NROWS * DD + idx * 4);
  float4 s; s.x = a.x + b.x; s.y = a.y + b.y; s.z = a.z + b.z; s.w = a.w + b.w;
  *(float4*)(out + idx * 4) = s;
}

// ---------------------------------------------------------------------------
// Entry point
// ---------------------------------------------------------------------------
extern "C" void kernel_launch(void* const* d_in, const int* in_sizes, int n_in,
                              void* d_out, int out_size) {
  const float* x    = (const float*)d_in[0];
  const float* Wq   = (const float*)d_in[1];
  const float* Wk   = (const float*)d_in[2];
  const float* Wv   = (const float*)d_in[3];
  const float* Wb   = (const float*)d_in[4];
  const float* Wtg  = (const float*)d_in[5];
  const float* ml   = (const float*)d_in[6];
  const float* ldc  = (const float*)d_in[7];
  const float* oms  = (const float*)d_in[8];
  const float* Wg   = (const float*)d_in[9];
  const float* Wo   = (const float*)d_in[10];
  float* out = (float*)d_out;

  proj_gemm_kernel<<<dim3(NPROJ / 64, NROWS / 64, 2), 256>>>(x, Wq, Wk, Wv, Wb, Wtg, Wg);
  proj_combine_kernel<<<(NROWS * NPROJ / 4 + 255) / 256, 256>>>();
  scan_kernel<<<BB * HH * RRm, 256>>>(ml, ldc, oms);
  reduce_y_kernel<<<(NROWS * 512 / 4 + 255) / 256, 256>>>();
  out_gemm_kernel<<<dim3(DD / 64, NROWS / 64, 2), 256>>>(Wo);
  out_sum_kernel<<<(NROWS * DD / 4 + 255) / 256, 256>>>(out);
}